// round 3
// baseline (speedup 1.0000x reference)
#include <cuda_runtime.h>
#include <math.h>

#define NB 8
#define CIN 256
#define HH 128
#define WW 128
#define HWSZ 16384
#define OCB 256
#define NCLS 18
#define NREG 36
#define BNEPS 1e-5f

// ---------------- scratch (device globals; no allocation allowed) ----------------
__device__ float sc_base[(size_t)NB * OCB * HWSZ];   // conv3x3+mish output (pre-BN), 134MB
__device__ float sc_cls[(size_t)NB * NCLS * HWSZ];   // 1x1 cls output (pre-BN)
__device__ float sc_reg[(size_t)NB * NREG * HWSZ];   // 1x1 reg output (pre-BN)
__device__ float sc_Wt[CIN * 9 * OCB];               // base weights transposed [(ci*9+k)][oc]
__device__ float sc_scaleA[CIN];                     // base BN scale (gamma*invstd)
__device__ float sc_shiftA[CIN];                     // base BN shift (beta - mean*scale)
__device__ float sc_Wf[(NCLS + NREG) * CIN];         // folded 1x1 weights
__device__ float sc_bf[NCLS + NREG];                 // folded 1x1 bias
__device__ float sc_s2[NCLS + NREG];                 // second BN scale
__device__ float sc_h2[NCLS + NREG];                 // second BN shift

// ---------------- helpers ----------------
__device__ __forceinline__ unsigned long long pk2(float v) {
    unsigned long long r; unsigned u = __float_as_uint(v);
    asm("mov.b64 %0, {%1, %2};" : "=l"(r) : "r"(u), "r"(u));
    return r;
}
__device__ __forceinline__ void fma2(unsigned long long& d, unsigned long long a, unsigned long long b) {
    asm("fma.rn.f32x2 %0, %1, %2, %0;" : "+l"(d) : "l"(a), "l"(b));
}
__device__ __forceinline__ float2 upk(unsigned long long v) {
    unsigned lo, hi;
    asm("mov.b64 {%0, %1}, %2;" : "=r"(lo), "=r"(hi) : "l"(v));
    return make_float2(__uint_as_float(lo), __uint_as_float(hi));
}
__device__ __forceinline__ float mishf(float v) {
    // softplus(x) = max(x,0) + log1p(exp(-|x|))  (matches jnp.logaddexp(x,0))
    float sp = fmaxf(v, 0.f) + log1pf(expf(-fabsf(v)));
    return v * tanhf(sp);
}
__device__ __forceinline__ float block_reduce(float v, float* red, int tid) {
    red[tid] = v; __syncthreads();
#pragma unroll
    for (int o = 128; o > 0; o >>= 1) {
        if (tid < o) red[tid] += red[tid + o];
        __syncthreads();
    }
    float r = red[0];
    __syncthreads();
    return r;
}

// ---------------- K0: transpose base conv weights to [(ci*9+k)][oc] ----------------
__global__ void k0_wt(const float* __restrict__ W) {
    int i = blockIdx.x * 256 + threadIdx.x;
    if (i < CIN * 9 * OCB) {
        int oc = i % OCB;
        int rk = i / OCB;            // ci*9 + k
        sc_Wt[i] = W[oc * (CIN * 9) + rk];
    }
}

// ---------------- K1: conv3x3 (pad 1) + bias + mish, f32x2 packed FMA ----------------
// grid: (64 spatial tiles 16x16, 4 oc-groups of 64, 8 images), 256 threads.
// thread: 8 oc (as 4 f32x2 pairs) x 8 positions (one half-row of the 16x16 tile).
__global__ void __launch_bounds__(256, 2) k1_conv(const float* __restrict__ x,
                                                  const float* __restrict__ pb) {
    __shared__ float s_in[8][18][20];   // cin-chunk x (16+2) rows x padded cols
    __shared__ float s_w[8][9][64];     // cin-chunk x k x oc
    int bx = blockIdx.x;
    int tx = bx & 7, ty = bx >> 3;
    int oc0 = blockIdx.y * 64;
    int n = blockIdx.z;
    int tid = threadIdx.x;
    int ocg = tid >> 5, posg = tid & 31;
    int py = posg >> 1, px8 = (posg & 1) << 3;
    int gy0 = ty * 16 - 1, gx0 = tx * 16 - 1;

    unsigned long long acc[4][8];
#pragma unroll
    for (int a = 0; a < 4; a++)
#pragma unroll
        for (int j = 0; j < 8; j++) acc[a][j] = 0ull;

    const float* xn = x + (size_t)n * CIN * HWSZ;

    for (int c0 = 0; c0 < CIN; c0 += 8) {
        __syncthreads();
        // stage input tile (zero-padded halo)
        for (int i = tid; i < 8 * 18 * 18; i += 256) {
            int ci = i / 324;
            int r = (i / 18) % 18;
            int c = i % 18;
            int gy = gy0 + r, gx = gx0 + c;
            float v = 0.f;
            if ((unsigned)gy < 128u && (unsigned)gx < 128u)
                v = xn[(size_t)(c0 + ci) * HWSZ + gy * WW + gx];
            s_in[ci][r][c] = v;
        }
        // stage weights (coalesced from transposed layout)
        for (int i = tid; i < 8 * 9 * 64; i += 256) {
            int oc = i & 63;
            int k = (i >> 6) % 9;
            int ci = i / 576;
            s_w[ci][k][oc] = sc_Wt[((c0 + ci) * 9 + k) * OCB + oc0 + oc];
        }
        __syncthreads();

#pragma unroll 2
        for (int ci = 0; ci < 8; ci++) {
#pragma unroll
            for (int dy = 0; dy < 3; dy++) {
                const float4* rp = reinterpret_cast<const float4*>(&s_in[ci][py + dy][px8]);
                float4 v0 = rp[0], v1 = rp[1], v2 = rp[2];
                float rr[10] = {v0.x, v0.y, v0.z, v0.w, v1.x, v1.y, v1.z, v1.w, v2.x, v2.y};
                unsigned long long p[10];
#pragma unroll
                for (int t = 0; t < 10; t++) p[t] = pk2(rr[t]);
#pragma unroll
                for (int dx = 0; dx < 3; dx++) {
                    unsigned sa = (unsigned)__cvta_generic_to_shared(&s_w[ci][dy * 3 + dx][ocg * 8]);
                    unsigned long long w01, w23, w45, w67;
                    asm("ld.shared.v2.u64 {%0,%1}, [%2];" : "=l"(w01), "=l"(w23) : "r"(sa));
                    asm("ld.shared.v2.u64 {%0,%1}, [%2+16];" : "=l"(w45), "=l"(w67) : "r"(sa));
#pragma unroll
                    for (int j = 0; j < 8; j++) {
                        unsigned long long a = p[j + dx];
                        fma2(acc[0][j], a, w01);
                        fma2(acc[1][j], a, w23);
                        fma2(acc[2][j], a, w45);
                        fma2(acc[3][j], a, w67);
                    }
                }
            }
        }
    }

    // epilogue: bias + mish -> sc_base (NCHW)
    int row = ty * 16 + py, colb = tx * 16 + px8;
#pragma unroll
    for (int a2 = 0; a2 < 4; a2++) {
        int ocl = oc0 + ocg * 8 + 2 * a2;
        float b0 = pb[ocl], b1 = pb[ocl + 1];
        float o0[8], o1[8];
#pragma unroll
        for (int j = 0; j < 8; j++) {
            float2 u = upk(acc[a2][j]);
            o0[j] = mishf(u.x + b0);
            o1[j] = mishf(u.y + b1);
        }
        float* d0 = &sc_base[(size_t)(n * OCB + ocl) * HWSZ + row * WW + colb];
        float* d1 = d0 + (size_t)HWSZ;
        *(float4*)d0 = make_float4(o0[0], o0[1], o0[2], o0[3]);
        *((float4*)d0 + 1) = make_float4(o0[4], o0[5], o0[6], o0[7]);
        *(float4*)d1 = make_float4(o1[0], o1[1], o1[2], o1[3]);
        *((float4*)d1 + 1) = make_float4(o1[4], o1[5], o1[6], o1[7]);
    }
}

// ---------------- K2: base BN stats (two-pass, deterministic) ----------------
__global__ void k2_base_stats(const float* __restrict__ gam, const float* __restrict__ bet) {
    __shared__ float red[256];
    int c = blockIdx.x, tid = threadIdx.x;
    float s = 0.f;
    for (int n = 0; n < NB; n++) {
        const float* p = &sc_base[(size_t)(n * OCB + c) * HWSZ];
        for (int i = tid; i < HWSZ; i += 256) s += p[i];
    }
    float mean = block_reduce(s, red, tid) * (1.f / (NB * HWSZ));
    s = 0.f;
    for (int n = 0; n < NB; n++) {
        const float* p = &sc_base[(size_t)(n * OCB + c) * HWSZ];
        for (int i = tid; i < HWSZ; i += 256) {
            float d = p[i] - mean;
            s += d * d;
        }
    }
    float var = block_reduce(s, red, tid) * (1.f / (NB * HWSZ));
    if (tid == 0) {
        float inv = rsqrtf(var + BNEPS);
        float scl = gam[c] * inv;
        sc_scaleA[c] = scl;
        sc_shiftA[c] = bet[c] - mean * scl;
    }
}

// ---------------- K3: fold base BN into 1x1 conv weights ----------------
__global__ void k3_fold(const float* __restrict__ Wc, const float* __restrict__ bc,
                        const float* __restrict__ Wr, const float* __restrict__ br) {
    __shared__ float red[256];
    int o = blockIdx.x, ci = threadIdx.x;
    const float* Ws;
    float bs;
    int ol;
    if (o < NCLS) { Ws = Wc; ol = o; bs = bc[o]; }
    else { Ws = Wr; ol = o - NCLS; bs = br[ol]; }
    float w = Ws[ol * CIN + ci];
    sc_Wf[o * CIN + ci] = w * sc_scaleA[ci];
    float tot = block_reduce(w * sc_shiftA[ci], red, ci);
    if (ci == 0) sc_bf[o] = bs + tot;
}

// ---------------- K4: 1x1 conv on folded weights ----------------
template <int NOUT, int NP, int PIX, int WHICH>
__global__ void k4_1x1() {
    extern __shared__ float sw[];  // [CIN][NP]
    const float* wf = sc_Wf + (WHICH ? NCLS * CIN : 0);
    const float* bf = sc_bf + (WHICH ? NCLS : 0);
    float* outp = WHICH ? sc_reg : sc_cls;
    int tid = threadIdx.x;
    for (int i = tid; i < CIN * NP; i += 256) {
        int c = i / NP, o = i % NP;
        sw[i] = (o < NOUT) ? wf[o * CIN + c] : 0.f;
    }
    __syncthreads();
    int pstart = blockIdx.x * (256 * PIX);
    int n = pstart >> 14;
    int hwb = (pstart & 16383) + tid;
    float acc[NP][PIX];
#pragma unroll
    for (int o = 0; o < NP; o++) {
        float b = (o < NOUT) ? bf[o] : 0.f;
#pragma unroll
        for (int px = 0; px < PIX; px++) acc[o][px] = b;
    }
    for (int c = 0; c < CIN; c++) {
        const float* bp = &sc_base[(size_t)(n * OCB + c) * HWSZ + hwb];
        float v[PIX];
#pragma unroll
        for (int px = 0; px < PIX; px++) v[px] = bp[px * 256];
#pragma unroll
        for (int o4 = 0; o4 < NP; o4 += 4) {
            float4 w = *reinterpret_cast<const float4*>(&sw[c * NP + o4]);
#pragma unroll
            for (int px = 0; px < PIX; px++) {
                acc[o4 + 0][px] += v[px] * w.x;
                acc[o4 + 1][px] += v[px] * w.y;
                acc[o4 + 2][px] += v[px] * w.z;
                acc[o4 + 3][px] += v[px] * w.w;
            }
        }
    }
#pragma unroll
    for (int o = 0; o < NOUT; o++)
#pragma unroll
        for (int px = 0; px < PIX; px++)
            outp[(size_t)(n * NOUT + o) * HWSZ + hwb + px * 256] = acc[o][px];
}

// ---------------- K5: cls/reg BN stats ----------------
__global__ void k5_stats2(const float* __restrict__ gc, const float* __restrict__ bc,
                          const float* __restrict__ gr, const float* __restrict__ br) {
    __shared__ float red[256];
    int b = blockIdx.x, tid = threadIdx.x;
    const float* src;
    int nch, ch;
    float gam, bet;
    if (b < NCLS) { src = sc_cls; nch = NCLS; ch = b; gam = gc[ch]; bet = bc[ch]; }
    else { src = sc_reg; nch = NREG; ch = b - NCLS; gam = gr[ch]; bet = br[ch]; }
    float s = 0.f;
    for (int n = 0; n < NB; n++) {
        const float* p = &src[(size_t)(n * nch + ch) * HWSZ];
        for (int i = tid; i < HWSZ; i += 256) s += p[i];
    }
    float mean = block_reduce(s, red, tid) * (1.f / (NB * HWSZ));
    s = 0.f;
    for (int n = 0; n < NB; n++) {
        const float* p = &src[(size_t)(n * nch + ch) * HWSZ];
        for (int i = tid; i < HWSZ; i += 256) {
            float d = p[i] - mean;
            s += d * d;
        }
    }
    float var = block_reduce(s, red, tid) * (1.f / (NB * HWSZ));
    if (tid == 0) {
        float inv = rsqrtf(var + BNEPS);
        float scl = gam * inv;
        sc_s2[b] = scl;
        sc_h2[b] = bet - mean * scl;
    }
}

// ---------------- K6: softmax + anchor decode ----------------
// anchors: base_size=40, ratios {0.5,1,2}, scales {8,16,32}; w_anc = W-1, h_anc = H-1
__constant__ float c_wa[9] = {455.f, 911.f, 1823.f, 319.f, 639.f, 1279.f, 223.f, 447.f, 895.f};
__constant__ float c_ha[9] = {223.f, 447.f, 895.f, 319.f, 639.f, 1279.f, 447.f, 895.f, 1791.f};

__global__ void k6_decode(const int* __restrict__ imgsz, float* __restrict__ out) {
    int t = blockIdx.x * 256 + threadIdx.x;
    if (t >= NB * HWSZ) return;
    int n = t >> 14, hw = t & 16383;
    int hy = hw >> 7, wx = hw & 127;
    float lim = 2048.f;
    if (imgsz) {
        int iv = *imgsz;
        lim = (iv > 0 && iv < (1 << 24)) ? (float)iv : __int_as_float(iv);
    }
    float cls[NCLS], rg[NREG];
#pragma unroll
    for (int o = 0; o < NCLS; o++)
        cls[o] = sc_cls[(size_t)(n * NCLS + o) * HWSZ + hw] * sc_s2[o] + sc_h2[o];
#pragma unroll
    for (int o = 0; o < NREG; o++)
        rg[o] = sc_reg[(size_t)(n * NREG + o) * HWSZ + hw] * sc_s2[NCLS + o] + sc_h2[NCLS + o];

    const size_t K = (size_t)HWSZ * 9;
    float* fg = out;
    float* ts = out + (size_t)NB * K;
    float* ro = ts + (size_t)NB * K * 4;
    size_t kb = (size_t)n * K + (size_t)hw * 9;

    float cxa = 19.5f + 16.f * (float)wx;
    float cya = 19.5f + 16.f * (float)hy;
#pragma unroll
    for (int a = 0; a < 9; a++) {
        float wa = c_wa[a], ha = c_ha[a];
        float x1 = fminf(fmaxf(rg[a * 4 + 0] + (cxa - 0.5f * wa), 0.f), lim);
        float y1 = fminf(fmaxf(rg[a * 4 + 1] + (cya - 0.5f * ha), 0.f), lim);
        float x2 = fminf(fmaxf(rg[a * 4 + 2] + (cxa + 0.5f * wa), 0.f), lim);
        float y2 = fminf(fmaxf(rg[a * 4 + 3] + (cya + 0.5f * ha), 0.f), lim);
        float w = x2 - x1, h = y2 - y1;
        float cx = x1 + 0.5f * w, cy = y1 + 0.5f * h;
        float s0 = cls[a * 2], s1 = cls[a * 2 + 1];
        fg[kb + a] = 1.f / (1.f + expf(s0 - s1));   // softmax(...)[:,1]
        size_t o4 = (kb + a) * 4;
        ts[o4 + 0] = (cx - cxa) / wa;
        ts[o4 + 1] = (cy - cya) / ha;
        ts[o4 + 2] = logf(fmaxf(w / wa, 1e-30f));
        ts[o4 + 3] = logf(fmaxf(h / ha, 1e-30f));
        ro[o4 + 0] = cx;
        ro[o4 + 1] = cy;
        ro[o4 + 2] = w;
        ro[o4 + 3] = h;
    }
}

// ---------------- launch ----------------
extern "C" void kernel_launch(void* const* d_in, const int* in_sizes, int n_in,
                              void* d_out, int out_size) {
    const float* x   = (const float*)d_in[0];
    const float* Wb  = (const float*)d_in[1];
    const float* bb  = (const float*)d_in[2];
    const float* gb  = (const float*)d_in[3];
    const float* beb = (const float*)d_in[4];
    const float* Wc  = (const float*)d_in[5];
    const float* bc  = (const float*)d_in[6];
    const float* gc  = (const float*)d_in[7];
    const float* bec = (const float*)d_in[8];
    const float* Wr  = (const float*)d_in[9];
    const float* br  = (const float*)d_in[10];
    const float* gr  = (const float*)d_in[11];
    const float* ber = (const float*)d_in[12];
    const int* imgsz = (n_in > 13) ? (const int*)d_in[13] : nullptr;
    float* out = (float*)d_out;

    k0_wt<<<(CIN * 9 * OCB + 255) / 256, 256>>>(Wb);

    dim3 g1(64, 4, NB);
    k1_conv<<<g1, 256>>>(x, bb);

    k2_base_stats<<<OCB, 256>>>(gb, beb);
    k3_fold<<<NCLS + NREG, 256>>>(Wc, bc, Wr, br);

    k4_1x1<NCLS, 20, 4, 0><<<NB * HWSZ / (256 * 4), 256, CIN * 20 * sizeof(float)>>>();
    k4_1x1<NREG, 36, 2, 1><<<NB * HWSZ / (256 * 2), 256, CIN * 36 * sizeof(float)>>>();

    k5_stats2<<<NCLS + NREG, 256>>>(gc, bec, gr, ber);
    k6_decode<<<NB * HWSZ / 256, 256>>>(imgsz, out);
}

// round 5
// speedup vs baseline: 2.3856x; 2.3856x over previous
#include <cuda_runtime.h>
#include <cstdint>
#include <math.h>

#define NB 8
#define CIN 256
#define HH 128
#define WW 128
#define HWSZ 16384
#define OCB 256
#define NCLS 18
#define NREG 36
#define BNEPS 1e-5f
#define PW 130          // padded H/W

// ---------------- scratch (device globals; zero-initialized at load) ----------------
__device__ float sc_pad[(size_t)NB * PW * PW * CIN];   // padded NHWC input, tf32-rounded (halo stays 0)
__device__ float sc_Wp[9 * OCB * CIN];                 // weights [tap][oc][ci], tf32-rounded
__device__ float sc_base[(size_t)NB * OCB * HWSZ];     // conv3x3+mish output (pre-BN), NCHW
__device__ float sc_cls[(size_t)NB * NCLS * HWSZ];
__device__ float sc_reg[(size_t)NB * NREG * HWSZ];
__device__ float sc_scaleA[CIN];
__device__ float sc_shiftA[CIN];
__device__ float sc_Wf[(NCLS + NREG) * CIN];
__device__ float sc_bf[NCLS + NREG];
__device__ float sc_s2[NCLS + NREG];
__device__ float sc_h2[NCLS + NREG];

// ---------------- helpers ----------------
__device__ __forceinline__ float tf32r(float v) {
    uint32_t u;
    asm("cvt.rna.tf32.f32 %0, %1;" : "=r"(u) : "f"(v));
    return __uint_as_float(u);
}
__device__ __forceinline__ void cpa16(void* dst, const void* src) {
    uint32_t d = (uint32_t)__cvta_generic_to_shared(dst);
    asm volatile("cp.async.cg.shared.global [%0], [%1], 16;" :: "r"(d), "l"(src));
}
__device__ __forceinline__ float mishf(float v) {
    float sp = fmaxf(v, 0.f) + log1pf(expf(-fabsf(v)));
    return v * tanhf(sp);
}
__device__ __forceinline__ float block_reduce(float v, float* red, int tid) {
    red[tid] = v; __syncthreads();
#pragma unroll
    for (int o = 128; o > 0; o >>= 1) {
        if (tid < o) red[tid] += red[tid + o];
        __syncthreads();
    }
    float r = red[0];
    __syncthreads();
    return r;
}

// ---------------- kP: NCHW -> padded NHWC (tf32-rounded) ----------------
__global__ void kP(const float* __restrict__ x) {
    __shared__ float t[32][33];
    int n = blockIdx.z, h = blockIdx.y, w0 = blockIdx.x * 32;
    int tid = threadIdx.x;
    int a = tid & 31, b = tid >> 5;  // b: 0..7
    for (int c0 = 0; c0 < CIN; c0 += 32) {
        __syncthreads();
#pragma unroll
        for (int j = 0; j < 4; j++) {
            int c = c0 + b + j * 8;
            t[b + j * 8][a] = x[(((size_t)n * CIN + c) * HH + h) * WW + w0 + a];
        }
        __syncthreads();
#pragma unroll
        for (int j = 0; j < 4; j++) {
            int w = w0 + b + j * 8;
            sc_pad[(((size_t)n * PW + (h + 1)) * PW + (w + 1)) * CIN + c0 + a] =
                tf32r(t[a][b + j * 8]);
        }
    }
}

// ---------------- kW: W[oc][ci][3][3] -> Wp[tap][oc][ci] (tf32-rounded) ----------------
__global__ void kW(const float* __restrict__ W) {
    int bi = blockIdx.x;            // 0..2303
    int oc = bi & 255, tap = bi >> 8;
    int ci = threadIdx.x;
    sc_Wp[((size_t)tap * OCB + oc) * CIN + ci] = tf32r(W[((size_t)oc * CIN + ci) * 9 + tap]);
}

// ---------------- kconv: tf32 mma.sync implicit GEMM ----------------
// CTA: 256 thr, 8 warps (wm 0..3 x wn 0..1). Tile M=256 (2 image rows) x N=128.
// Stage (24 total = 3 dy x 8 ci-chunks): A[260 pos][32ci] pad36, B[3 dx][128 oc][32ci] pad36.
// smem floats: A buf 9360, B buf 13824; A0=0 A1=9360 B0=18720 B1=32544; total 46368 (185472 B)
#define AF 9360
#define BF 13824
#define B0OFF 18720
#define CONV_SMEM (46368 * 4)

__device__ __forceinline__ void issue_stage(const float* __restrict__ pad_n, int by, int h0,
                                            int stage, float* sm, int buf, int tid) {
    int dy = stage >> 3, chunk = stage & 7;
    float* A = sm + buf * AF;
    float* B = sm + B0OFF + buf * BF;
    for (int i = tid; i < 2080; i += 256) {
        int pos = i >> 3, q = i & 7;
        int r = pos / 130, j = pos - r * 130;
        const float* src = pad_n + ((size_t)(h0 + r + dy) * PW + j) * CIN + chunk * 32 + q * 4;
        cpa16(A + pos * 36 + q * 4, src);
    }
    for (int i = tid; i < 3072; i += 256) {
        int dx = i >> 10, rem = i & 1023;
        int ocl = rem >> 3, q = rem & 7;
        const float* src = sc_Wp + ((size_t)((dy * 3 + dx) * OCB + by * 128 + ocl)) * CIN
                           + chunk * 32 + q * 4;
        cpa16(B + dx * 4608 + ocl * 36 + q * 4, src);
    }
}

__global__ void __launch_bounds__(256, 1) kconv(const float* __restrict__ pb) {
    extern __shared__ float sm[];
    int tid = threadIdx.x, lane = tid & 31, wid = tid >> 5;
    int wm = wid & 3, wn = wid >> 2;
    int s = blockIdx.x;
    int n = s >> 6, h0 = (s & 63) * 2;
    int by = blockIdx.y;
    const float* pad_n = sc_pad + (size_t)n * PW * PW * CIN;

    float acc[4][8][4];
#pragma unroll
    for (int a = 0; a < 4; a++)
#pragma unroll
        for (int b = 0; b < 8; b++)
#pragma unroll
            for (int c = 0; c < 4; c++) acc[a][b][c] = 0.f;

    int mrow = lane >> 2, kc = lane & 3;
    int wbase = (wm >> 1) * 130 + (wm & 1) * 64;      // + mf*16 + mrow + dx
    int ocl0 = wn * 64 + mrow;                        // + nf*8

    issue_stage(pad_n, by, h0, 0, sm, 0, tid);
    asm volatile("cp.async.commit_group;" ::: "memory");

#pragma unroll 1
    for (int st = 0; st < 24; st++) {
        if (st + 1 < 24) {
            issue_stage(pad_n, by, h0, st + 1, sm, (st + 1) & 1, tid);
            asm volatile("cp.async.commit_group;" ::: "memory");
            asm volatile("cp.async.wait_group 1;" ::: "memory");
        } else {
            asm volatile("cp.async.wait_group 0;" ::: "memory");
        }
        __syncthreads();

        const float* A = sm + (st & 1) * AF;
        const float* B = sm + B0OFF + (st & 1) * BF;
#pragma unroll
        for (int dx = 0; dx < 3; dx++) {
#pragma unroll
            for (int ks = 0; ks < 4; ks++) {
                uint32_t af[4][4];
#pragma unroll
                for (int mf = 0; mf < 4; mf++) {
                    const float* p0 = A + (wbase + mf * 16 + mrow + dx) * 36 + ks * 8 + kc;
                    af[mf][0] = __float_as_uint(p0[0]);
                    af[mf][1] = __float_as_uint(p0[8 * 36]);
                    af[mf][2] = __float_as_uint(p0[4]);
                    af[mf][3] = __float_as_uint(p0[8 * 36 + 4]);
                }
                uint32_t bf[8][2];
#pragma unroll
                for (int nf = 0; nf < 8; nf++) {
                    const float* pb2 = B + dx * 4608 + (ocl0 + nf * 8) * 36 + ks * 8 + kc;
                    bf[nf][0] = __float_as_uint(pb2[0]);
                    bf[nf][1] = __float_as_uint(pb2[4]);
                }
#pragma unroll
                for (int mf = 0; mf < 4; mf++)
#pragma unroll
                    for (int nf = 0; nf < 8; nf++)
                        asm volatile(
                            "mma.sync.aligned.m16n8k8.row.col.f32.tf32.tf32.f32 "
                            "{%0,%1,%2,%3}, {%4,%5,%6,%7}, {%8,%9}, {%0,%1,%2,%3};"
                            : "+f"(acc[mf][nf][0]), "+f"(acc[mf][nf][1]),
                              "+f"(acc[mf][nf][2]), "+f"(acc[mf][nf][3])
                            : "r"(af[mf][0]), "r"(af[mf][1]), "r"(af[mf][2]), "r"(af[mf][3]),
                              "r"(bf[nf][0]), "r"(bf[nf][1]));
            }
        }
        __syncthreads();
    }

    // epilogue: bias + mish -> sc_base NCHW
    int h = h0 + (wm >> 1);
#pragma unroll
    for (int mf = 0; mf < 4; mf++) {
        int w = (wm & 1) * 64 + mf * 16 + mrow;
#pragma unroll
        for (int nf = 0; nf < 8; nf++) {
            int oc = by * 128 + wn * 64 + nf * 8 + 2 * kc;
            float b0v = pb[oc], b1v = pb[oc + 1];
            float* p = sc_base + ((size_t)(n * OCB + oc)) * HWSZ + h * WW + w;
            p[0] = mishf(acc[mf][nf][0] + b0v);
            p[HWSZ] = mishf(acc[mf][nf][1] + b1v);
            p[8] = mishf(acc[mf][nf][2] + b0v);
            p[HWSZ + 8] = mishf(acc[mf][nf][3] + b1v);
        }
    }
}

// ---------------- K2: base BN stats ----------------
__global__ void k2_base_stats(const float* __restrict__ gam, const float* __restrict__ bet) {
    __shared__ float red[256];
    int c = blockIdx.x, tid = threadIdx.x;
    float s = 0.f;
    for (int n = 0; n < NB; n++) {
        const float* p = &sc_base[(size_t)(n * OCB + c) * HWSZ];
        for (int i = tid; i < HWSZ; i += 256) s += p[i];
    }
    float mean = block_reduce(s, red, tid) * (1.f / (NB * HWSZ));
    s = 0.f;
    for (int n = 0; n < NB; n++) {
        const float* p = &sc_base[(size_t)(n * OCB + c) * HWSZ];
        for (int i = tid; i < HWSZ; i += 256) {
            float d = p[i] - mean;
            s += d * d;
        }
    }
    float var = block_reduce(s, red, tid) * (1.f / (NB * HWSZ));
    if (tid == 0) {
        float inv = rsqrtf(var + BNEPS);
        float scl = gam[c] * inv;
        sc_scaleA[c] = scl;
        sc_shiftA[c] = bet[c] - mean * scl;
    }
}

// ---------------- K3: fold base BN into 1x1 conv weights ----------------
__global__ void k3_fold(const float* __restrict__ Wc, const float* __restrict__ bc,
                        const float* __restrict__ Wr, const float* __restrict__ br) {
    __shared__ float red[256];
    int o = blockIdx.x, ci = threadIdx.x;
    const float* Ws;
    float bs;
    int ol;
    if (o < NCLS) { Ws = Wc; ol = o; bs = bc[o]; }
    else { Ws = Wr; ol = o - NCLS; bs = br[ol]; }
    float w = Ws[ol * CIN + ci];
    sc_Wf[o * CIN + ci] = w * sc_scaleA[ci];
    float tot = block_reduce(w * sc_shiftA[ci], red, ci);
    if (ci == 0) sc_bf[o] = bs + tot;
}

// ---------------- K4: 1x1 conv on folded weights ----------------
template <int NOUT, int NP, int PIX, int WHICH>
__global__ void k4_1x1() {
    extern __shared__ float sw[];
    const float* wf = sc_Wf + (WHICH ? NCLS * CIN : 0);
    const float* bf = sc_bf + (WHICH ? NCLS : 0);
    float* outp = WHICH ? sc_reg : sc_cls;
    int tid = threadIdx.x;
    for (int i = tid; i < CIN * NP; i += 256) {
        int c = i / NP, o = i % NP;
        sw[i] = (o < NOUT) ? wf[o * CIN + c] : 0.f;
    }
    __syncthreads();
    int pstart = blockIdx.x * (256 * PIX);
    int n = pstart >> 14;
    int hwb = (pstart & 16383) + tid;
    float acc[NP][PIX];
#pragma unroll
    for (int o = 0; o < NP; o++) {
        float b = (o < NOUT) ? bf[o] : 0.f;
#pragma unroll
        for (int px = 0; px < PIX; px++) acc[o][px] = b;
    }
    for (int c = 0; c < CIN; c++) {
        const float* bp = &sc_base[(size_t)(n * OCB + c) * HWSZ + hwb];
        float v[PIX];
#pragma unroll
        for (int px = 0; px < PIX; px++) v[px] = bp[px * 256];
#pragma unroll
        for (int o4 = 0; o4 < NP; o4 += 4) {
            float4 w = *reinterpret_cast<const float4*>(&sw[c * NP + o4]);
#pragma unroll
            for (int px = 0; px < PIX; px++) {
                acc[o4 + 0][px] += v[px] * w.x;
                acc[o4 + 1][px] += v[px] * w.y;
                acc[o4 + 2][px] += v[px] * w.z;
                acc[o4 + 3][px] += v[px] * w.w;
            }
        }
    }
#pragma unroll
    for (int o = 0; o < NOUT; o++)
#pragma unroll
        for (int px = 0; px < PIX; px++)
            outp[(size_t)(n * NOUT + o) * HWSZ + hwb + px * 256] = acc[o][px];
}

// ---------------- K5: cls/reg BN stats ----------------
__global__ void k5_stats2(const float* __restrict__ gc, const float* __restrict__ bc,
                          const float* __restrict__ gr, const float* __restrict__ br) {
    __shared__ float red[256];
    int b = blockIdx.x, tid = threadIdx.x;
    const float* src;
    int nch, ch;
    float gam, bet;
    if (b < NCLS) { src = sc_cls; nch = NCLS; ch = b; gam = gc[ch]; bet = bc[ch]; }
    else { src = sc_reg; nch = NREG; ch = b - NCLS; gam = gr[ch]; bet = br[ch]; }
    float s = 0.f;
    for (int n = 0; n < NB; n++) {
        const float* p = &src[(size_t)(n * nch + ch) * HWSZ];
        for (int i = tid; i < HWSZ; i += 256) s += p[i];
    }
    float mean = block_reduce(s, red, tid) * (1.f / (NB * HWSZ));
    s = 0.f;
    for (int n = 0; n < NB; n++) {
        const float* p = &src[(size_t)(n * nch + ch) * HWSZ];
        for (int i = tid; i < HWSZ; i += 256) {
            float d = p[i] - mean;
            s += d * d;
        }
    }
    float var = block_reduce(s, red, tid) * (1.f / (NB * HWSZ));
    if (tid == 0) {
        float inv = rsqrtf(var + BNEPS);
        float scl = gam * inv;
        sc_s2[b] = scl;
        sc_h2[b] = bet - mean * scl;
    }
}

// ---------------- K6: softmax + anchor decode ----------------
__constant__ float c_wa[9] = {455.f, 911.f, 1823.f, 319.f, 639.f, 1279.f, 223.f, 447.f, 895.f};
__constant__ float c_ha[9] = {223.f, 447.f, 895.f, 319.f, 639.f, 1279.f, 447.f, 895.f, 1791.f};

__global__ void k6_decode(const int* __restrict__ imgsz, float* __restrict__ out) {
    int t = blockIdx.x * 256 + threadIdx.x;
    if (t >= NB * HWSZ) return;
    int n = t >> 14, hw = t & 16383;
    int hy = hw >> 7, wx = hw & 127;
    float lim = 2048.f;
    if (imgsz) {
        int iv = *imgsz;
        lim = (iv > 0 && iv < (1 << 24)) ? (float)iv : __int_as_float(iv);
    }
    float cls[NCLS], rg[NREG];
#pragma unroll
    for (int o = 0; o < NCLS; o++)
        cls[o] = sc_cls[(size_t)(n * NCLS + o) * HWSZ + hw] * sc_s2[o] + sc_h2[o];
#pragma unroll
    for (int o = 0; o < NREG; o++)
        rg[o] = sc_reg[(size_t)(n * NREG + o) * HWSZ + hw] * sc_s2[NCLS + o] + sc_h2[NCLS + o];

    const size_t K = (size_t)HWSZ * 9;
    float* fg = out;
    float* ts = out + (size_t)NB * K;
    float* ro = ts + (size_t)NB * K * 4;
    size_t kb = (size_t)n * K + (size_t)hw * 9;

    float cxa = 19.5f + 16.f * (float)wx;
    float cya = 19.5f + 16.f * (float)hy;
#pragma unroll
    for (int a = 0; a < 9; a++) {
        float wa = c_wa[a], ha = c_ha[a];
        float x1 = fminf(fmaxf(rg[a * 4 + 0] + (cxa - 0.5f * wa), 0.f), lim);
        float y1 = fminf(fmaxf(rg[a * 4 + 1] + (cya - 0.5f * ha), 0.f), lim);
        float x2 = fminf(fmaxf(rg[a * 4 + 2] + (cxa + 0.5f * wa), 0.f), lim);
        float y2 = fminf(fmaxf(rg[a * 4 + 3] + (cya + 0.5f * ha), 0.f), lim);
        float w = x2 - x1, h = y2 - y1;
        float cx = x1 + 0.5f * w, cy = y1 + 0.5f * h;
        float s0 = cls[a * 2], s1 = cls[a * 2 + 1];
        fg[kb + a] = 1.f / (1.f + expf(s0 - s1));
        size_t o4 = (kb + a) * 4;
        ts[o4 + 0] = (cx - cxa) / wa;
        ts[o4 + 1] = (cy - cya) / ha;
        ts[o4 + 2] = logf(fmaxf(w / wa, 1e-30f));
        ts[o4 + 3] = logf(fmaxf(h / ha, 1e-30f));
        ro[o4 + 0] = cx;
        ro[o4 + 1] = cy;
        ro[o4 + 2] = w;
        ro[o4 + 3] = h;
    }
}

// ---------------- launch ----------------
extern "C" void kernel_launch(void* const* d_in, const int* in_sizes, int n_in,
                              void* d_out, int out_size) {
    const float* x   = (const float*)d_in[0];
    const float* Wb  = (const float*)d_in[1];
    const float* bb  = (const float*)d_in[2];
    const float* gb  = (const float*)d_in[3];
    const float* beb = (const float*)d_in[4];
    const float* Wc  = (const float*)d_in[5];
    const float* bc  = (const float*)d_in[6];
    const float* gc  = (const float*)d_in[7];
    const float* bec = (const float*)d_in[8];
    const float* Wr  = (const float*)d_in[9];
    const float* br  = (const float*)d_in[10];
    const float* gr  = (const float*)d_in[11];
    const float* ber = (const float*)d_in[12];
    const int* imgsz = (n_in > 13) ? (const int*)d_in[13] : nullptr;
    float* out = (float*)d_out;

    static int smem_set = 0;
    if (!smem_set) {
        cudaFuncSetAttribute(kconv, cudaFuncAttributeMaxDynamicSharedMemorySize, CONV_SMEM);
        smem_set = 1;
    }

    dim3 gp(4, 128, NB);
    kP<<<gp, 256>>>(x);
    kW<<<9 * OCB, 256>>>(Wb);

    dim3 gc2(512, 2);
    kconv<<<gc2, 256, CONV_SMEM>>>(bb);

    k2_base_stats<<<OCB, 256>>>(gb, beb);
    k3_fold<<<NCLS + NREG, 256>>>(Wc, bc, Wr, br);

    k4_1x1<NCLS, 20, 4, 0><<<NB * HWSZ / (256 * 4), 256, CIN * 20 * sizeof(float)>>>();
    k4_1x1<NREG, 36, 2, 1><<<NB * HWSZ / (256 * 2), 256, CIN * 36 * sizeof(float)>>>();

    k5_stats2<<<NCLS + NREG, 256>>>(gc, bec, gr, ber);
    k6_decode<<<NB * HWSZ / 256, 256>>>(imgsz, out);
}

// round 6
// speedup vs baseline: 2.5622x; 1.0740x over previous
#include <cuda_runtime.h>
#include <cstdint>
#include <math.h>

#define NB 8
#define CIN 256
#define HH 128
#define WW 128
#define HWSZ 16384
#define OCB 256
#define NCLS 18
#define NREG 36
#define NTOT 54
#define BNEPS 1e-5f
#define PW 130          // padded H/W

// ---------------- scratch (device globals; zero-initialized at load) ----------------
__device__ float sc_pad[(size_t)NB * PW * PW * CIN];   // padded NHWC input, tf32-rounded, k-pair-permuted
__device__ float sc_Wp[9 * OCB * CIN];                 // weights [tap][oc][ci], tf32-rounded, k-pair-permuted
__device__ float sc_base[(size_t)NB * OCB * HWSZ];     // conv3x3+mish output (pre-BN), NCHW
__device__ float sc_part[256][512][2];                 // per-CTA (sum, sumsq) partials per channel
__device__ float sc_cls[(size_t)NB * NCLS * HWSZ];
__device__ float sc_reg[(size_t)NB * NREG * HWSZ];
__device__ float sc_scaleA[CIN];
__device__ float sc_shiftA[CIN];
__device__ float sc_Wf[NTOT * CIN];
__device__ float sc_bf[NTOT];
__device__ float sc_s2[NTOT];
__device__ float sc_h2[NTOT];

// ---------------- helpers ----------------
__device__ __forceinline__ float tf32r(float v) {
    uint32_t u;
    asm("cvt.rna.tf32.f32 %0, %1;" : "=r"(u) : "f"(v));
    return __uint_as_float(u);
}
__device__ __forceinline__ void cpa16(void* dst, const void* src) {
    uint32_t d = (uint32_t)__cvta_generic_to_shared(dst);
    asm volatile("cp.async.cg.shared.global [%0], [%1], 16;" :: "r"(d), "l"(src));
}
__device__ __forceinline__ unsigned long long pk2(float v) {
    unsigned long long r; unsigned u = __float_as_uint(v);
    asm("mov.b64 %0, {%1, %2};" : "=l"(r) : "r"(u), "r"(u));
    return r;
}
__device__ __forceinline__ unsigned long long pk2ab(float a, float b) {
    unsigned long long r;
    asm("mov.b64 %0, {%1, %2};" : "=l"(r) : "r"(__float_as_uint(a)), "r"(__float_as_uint(b)));
    return r;
}
__device__ __forceinline__ void fma2(unsigned long long& d, unsigned long long a, unsigned long long b) {
    asm("fma.rn.f32x2 %0, %1, %2, %0;" : "+l"(d) : "l"(a), "l"(b));
}
__device__ __forceinline__ float2 upk(unsigned long long v) {
    unsigned lo, hi;
    asm("mov.b64 {%0, %1}, %2;" : "=r"(lo), "=r"(hi) : "l"(v));
    return make_float2(__uint_as_float(lo), __uint_as_float(hi));
}
__device__ __forceinline__ float mishf(float v) {
    float sp = fmaxf(v, 0.f) + log1pf(expf(-fabsf(v)));
    return v * tanhf(sp);
}
__device__ __forceinline__ float block_reduce(float v, float* red, int tid) {
    red[tid] = v; __syncthreads();
#pragma unroll
    for (int o = 128; o > 0; o >>= 1) {
        if (tid < o) red[tid] += red[tid + o];
        __syncthreads();
    }
    float r = red[0];
    __syncthreads();
    return r;
}
// within-32 k-pair permutation: k=ks*8+half*4+kc -> ks*8+kc*2+half
__device__ __forceinline__ int pidx32(int k) {
    return (k & 24) + (k & 3) * 2 + ((k >> 2) & 1);
}

// ---------------- kP: NCHW -> padded NHWC (tf32-rounded, k-permuted) ----------------
__global__ void kP(const float* __restrict__ x) {
    __shared__ float t[32][33];
    int n = blockIdx.z, h = blockIdx.y, w0 = blockIdx.x * 32;
    int tid = threadIdx.x;
    int a = tid & 31, b = tid >> 5;  // b: 0..7
    int pa = pidx32(a);
    for (int c0 = 0; c0 < CIN; c0 += 32) {
        __syncthreads();
#pragma unroll
        for (int j = 0; j < 4; j++) {
            int c = c0 + b + j * 8;
            t[b + j * 8][a] = x[(((size_t)n * CIN + c) * HH + h) * WW + w0 + a];
        }
        __syncthreads();
#pragma unroll
        for (int j = 0; j < 4; j++) {
            int w = w0 + b + j * 8;
            sc_pad[(((size_t)n * PW + (h + 1)) * PW + (w + 1)) * CIN + c0 + pa] =
                tf32r(t[a][b + j * 8]);
        }
    }
}

// ---------------- kW: W[oc][ci][3][3] -> Wp[tap][oc][ci] (tf32-rounded, k-permuted) ----------------
__global__ void kW(const float* __restrict__ W) {
    int bi = blockIdx.x;            // 0..2303
    int oc = bi & 255, tap = bi >> 8;
    int ci = threadIdx.x;
    int pci = (ci & ~31) | pidx32(ci & 31);
    sc_Wp[((size_t)tap * OCB + oc) * CIN + pci] = tf32r(W[((size_t)oc * CIN + ci) * 9 + tap]);
}

// ---------------- kconv: tf32 mma.sync implicit GEMM, vectorized frags + fused stats ----------------
// CTA: 256 thr, 8 warps (wm 0..3 x wn 0..1). Tile M=256 (2 image rows) x N=128.
// Stage: A[260 pos][40], B[3 dx][128 oc][40] (pair layout: k -> ks*8+kc*2+half)
#define AF 10400
#define BF 15360
#define B0OFF 20800
#define CONV_SMEM (51520 * 4)

__device__ __forceinline__ void issue_stage(const float* __restrict__ pad_n, int by, int h0,
                                            int stage, float* sm, int buf, int tid) {
    int dy = stage >> 3, chunk = stage & 7;
    float* A = sm + buf * AF;
    float* B = sm + B0OFF + buf * BF;
    for (int i = tid; i < 2080; i += 256) {
        int pos = i >> 3, q = i & 7;
        int r = pos / 130, j = pos - r * 130;
        const float* src = pad_n + ((size_t)(h0 + r + dy) * PW + j) * CIN + chunk * 32 + q * 4;
        cpa16(A + pos * 40 + q * 4, src);
    }
    for (int i = tid; i < 3072; i += 256) {
        int dx = i >> 10, rem = i & 1023;
        int ocl = rem >> 3, q = rem & 7;
        const float* src = sc_Wp + ((size_t)((dy * 3 + dx) * OCB + by * 128 + ocl)) * CIN
                           + chunk * 32 + q * 4;
        cpa16(B + dx * 5120 + ocl * 40 + q * 4, src);
    }
}

__global__ void __launch_bounds__(256, 1) kconv(const float* __restrict__ pb) {
    extern __shared__ float sm[];
    int tid = threadIdx.x, lane = tid & 31;
    int wid = tid >> 5;
    int wm = wid & 3, wn = wid >> 2;
    int s = blockIdx.x;
    int n = s >> 6, h0 = (s & 63) * 2;
    int by = blockIdx.y;
    const float* pad_n = sc_pad + (size_t)n * PW * PW * CIN;

    float acc[4][8][4];
#pragma unroll
    for (int a = 0; a < 4; a++)
#pragma unroll
        for (int b = 0; b < 8; b++)
#pragma unroll
            for (int c = 0; c < 4; c++) acc[a][b][c] = 0.f;

    int mrow = lane >> 2, kc = lane & 3;
    int wbase = (wm >> 1) * 130 + (wm & 1) * 64;
    int ocl0 = wn * 64 + mrow;

    issue_stage(pad_n, by, h0, 0, sm, 0, tid);
    asm volatile("cp.async.commit_group;" ::: "memory");

#pragma unroll 1
    for (int st = 0; st < 24; st++) {
        if (st + 1 < 24) {
            issue_stage(pad_n, by, h0, st + 1, sm, (st + 1) & 1, tid);
            asm volatile("cp.async.commit_group;" ::: "memory");
            asm volatile("cp.async.wait_group 1;" ::: "memory");
        } else {
            asm volatile("cp.async.wait_group 0;" ::: "memory");
        }
        __syncthreads();

        const float* A = sm + (st & 1) * AF;
        const float* B = sm + B0OFF + (st & 1) * BF;
#pragma unroll
        for (int dx = 0; dx < 3; dx++) {
#pragma unroll
            for (int ks = 0; ks < 4; ks++) {
                uint32_t af[4][4];
#pragma unroll
                for (int mf = 0; mf < 4; mf++) {
                    const float* p0 = A + (wbase + mf * 16 + mrow + dx) * 40 + ks * 8 + kc * 2;
                    float2 lo = *(const float2*)p0;          // (a0, a2)
                    float2 hi = *(const float2*)(p0 + 320);  // (a1, a3) row+8
                    af[mf][0] = __float_as_uint(lo.x);
                    af[mf][1] = __float_as_uint(hi.x);
                    af[mf][2] = __float_as_uint(lo.y);
                    af[mf][3] = __float_as_uint(hi.y);
                }
                uint32_t bfr[8][2];
#pragma unroll
                for (int nf = 0; nf < 8; nf++) {
                    float2 bv = *(const float2*)(B + dx * 5120 + (ocl0 + nf * 8) * 40
                                                 + ks * 8 + kc * 2);
                    bfr[nf][0] = __float_as_uint(bv.x);
                    bfr[nf][1] = __float_as_uint(bv.y);
                }
#pragma unroll
                for (int mf = 0; mf < 4; mf++)
#pragma unroll
                    for (int nf = 0; nf < 8; nf++)
                        asm volatile(
                            "mma.sync.aligned.m16n8k8.row.col.f32.tf32.tf32.f32 "
                            "{%0,%1,%2,%3}, {%4,%5,%6,%7}, {%8,%9}, {%0,%1,%2,%3};"
                            : "+f"(acc[mf][nf][0]), "+f"(acc[mf][nf][1]),
                              "+f"(acc[mf][nf][2]), "+f"(acc[mf][nf][3])
                            : "r"(af[mf][0]), "r"(af[mf][1]), "r"(af[mf][2]), "r"(af[mf][3]),
                              "r"(bfr[nf][0]), "r"(bfr[nf][1]));
            }
        }
        __syncthreads();
    }

    // epilogue: bias + mish -> sc_base NCHW, plus deterministic per-channel stats partials
    int h = h0 + (wm >> 1);
    float ssum[8][2], ssq[8][2];
#pragma unroll
    for (int nf = 0; nf < 8; nf++) {
        ssum[nf][0] = ssum[nf][1] = 0.f;
        ssq[nf][0] = ssq[nf][1] = 0.f;
    }
#pragma unroll
    for (int mf = 0; mf < 4; mf++) {
        int w = (wm & 1) * 64 + mf * 16 + mrow;
#pragma unroll
        for (int nf = 0; nf < 8; nf++) {
            int oc = by * 128 + wn * 64 + nf * 8 + 2 * kc;
            float b0v = pb[oc], b1v = pb[oc + 1];
            float v0 = mishf(acc[mf][nf][0] + b0v);
            float v1 = mishf(acc[mf][nf][1] + b1v);
            float v2 = mishf(acc[mf][nf][2] + b0v);
            float v3 = mishf(acc[mf][nf][3] + b1v);
            float* p = sc_base + ((size_t)(n * OCB + oc)) * HWSZ + h * WW + w;
            p[0] = v0; p[HWSZ] = v1; p[8] = v2; p[HWSZ + 8] = v3;
            ssum[nf][0] += v0 + v2;  ssq[nf][0] += v0 * v0 + v2 * v2;
            ssum[nf][1] += v1 + v3;  ssq[nf][1] += v1 * v1 + v3 * v3;
        }
    }
    // reduce over mrow (lanes stride 4, fixed order)
#pragma unroll
    for (int off = 4; off <= 16; off <<= 1) {
#pragma unroll
        for (int nf = 0; nf < 8; nf++)
#pragma unroll
            for (int j = 0; j < 2; j++) {
                ssum[nf][j] += __shfl_xor_sync(0xffffffffu, ssum[nf][j], off);
                ssq[nf][j] += __shfl_xor_sync(0xffffffffu, ssq[nf][j], off);
            }
    }
    float* part = sm;  // overlay [wn][wm][64 chl][2]
    if (mrow == 0) {
#pragma unroll
        for (int nf = 0; nf < 8; nf++)
#pragma unroll
            for (int j = 0; j < 2; j++) {
                int chl = nf * 8 + 2 * kc + j;
                part[((wn * 4 + wm) * 64 + chl) * 2 + 0] = ssum[nf][j];
                part[((wn * 4 + wm) * 64 + chl) * 2 + 1] = ssq[nf][j];
            }
    }
    __syncthreads();
    {
        int wn2 = tid >> 7, chl = (tid >> 1) & 63, v = tid & 1;
        float t = 0.f;
#pragma unroll
        for (int wm2 = 0; wm2 < 4; wm2++)
            t += part[((wn2 * 4 + wm2) * 64 + chl) * 2 + v];
        sc_part[by * 128 + wn2 * 64 + chl][s][v] = t;
    }
}

// ---------------- K2: base BN stats from partials (deterministic fixed-order) ----------------
__global__ void k2_base_stats(const float* __restrict__ gam, const float* __restrict__ bet) {
    __shared__ float red[256];
    int c = blockIdx.x, tid = threadIdx.x;
    float s = sc_part[c][tid][0] + sc_part[c][tid + 256][0];
    float sum = block_reduce(s, red, tid);
    float q = sc_part[c][tid][1] + sc_part[c][tid + 256][1];
    float sq = block_reduce(q, red, tid);
    if (tid == 0) {
        float inv_n = 1.f / (float)(NB * HWSZ);
        float mean = sum * inv_n;
        float var = sq * inv_n - mean * mean;
        float inv = rsqrtf(var + BNEPS);
        float scl = gam[c] * inv;
        sc_scaleA[c] = scl;
        sc_shiftA[c] = bet[c] - mean * scl;
    }
}

// ---------------- K3: fold base BN into 1x1 conv weights ----------------
__global__ void k3_fold(const float* __restrict__ Wc, const float* __restrict__ bc,
                        const float* __restrict__ Wr, const float* __restrict__ br) {
    __shared__ float red[256];
    int o = blockIdx.x, ci = threadIdx.x;
    const float* Ws;
    float bs;
    int ol;
    if (o < NCLS) { Ws = Wc; ol = o; bs = bc[o]; }
    else { Ws = Wr; ol = o - NCLS; bs = br[ol]; }
    float w = Ws[ol * CIN + ci];
    sc_Wf[o * CIN + ci] = w * sc_scaleA[ci];
    float tot = block_reduce(w * sc_shiftA[ci], red, ci);
    if (ci == 0) sc_bf[o] = bs + tot;
}

// ---------------- K4m: merged 1x1 convs (cls+reg), f32x2 packed, single read of sc_base ----------------
#define K4_SMEM (CIN * 56 * 4)
__global__ void __launch_bounds__(256) k4m() {
    extern __shared__ float swf[];  // [c][56]
    int tid = threadIdx.x;
    for (int i = tid; i < CIN * 56; i += 256) {
        int c = i / 56, o = i - c * 56;
        swf[i] = (o < NTOT) ? sc_Wf[o * CIN + c] : 0.f;
    }
    __syncthreads();
    int pstart = blockIdx.x * 512;     // 256 thr x 2 px
    int n = pstart >> 14;
    int hwb = (pstart & 16383) + tid;  // px at hwb, hwb+256

    unsigned long long acc2[27][2];
#pragma unroll
    for (int op = 0; op < 27; op++) {
        unsigned long long b = pk2ab(sc_bf[2 * op], sc_bf[2 * op + 1]);
        acc2[op][0] = b;
        acc2[op][1] = b;
    }
    const float* bpn = sc_base + (size_t)n * OCB * HWSZ + hwb;
#pragma unroll 1
    for (int c = 0; c < CIN; c += 8) {
        float v0[8], v1[8];
#pragma unroll
        for (int u = 0; u < 8; u++) {
            const float* p = bpn + (size_t)(c + u) * HWSZ;
            v0[u] = p[0];
            v1[u] = p[256];
        }
#pragma unroll
        for (int u = 0; u < 8; u++) {
            unsigned long long p0 = pk2(v0[u]), p1 = pk2(v1[u]);
            const unsigned long long* wrow = (const unsigned long long*)(swf + (c + u) * 56);
#pragma unroll
            for (int op = 0; op < 27; op++) {
                unsigned long long w = wrow[op];
                fma2(acc2[op][0], w, p0);
                fma2(acc2[op][1], w, p1);
            }
        }
    }
#pragma unroll
    for (int op = 0; op < 27; op++)
#pragma unroll
        for (int px = 0; px < 2; px++) {
            float2 u = upk(acc2[op][px]);
            int ch0 = 2 * op, ch1 = 2 * op + 1;
            size_t idx = hwb + px * 256;
            if (ch0 < NCLS) sc_cls[(size_t)(n * NCLS + ch0) * HWSZ + idx] = u.x;
            else sc_reg[(size_t)(n * NREG + (ch0 - NCLS)) * HWSZ + idx] = u.x;
            if (ch1 < NCLS) sc_cls[(size_t)(n * NCLS + ch1) * HWSZ + idx] = u.y;
            else sc_reg[(size_t)(n * NREG + (ch1 - NCLS)) * HWSZ + idx] = u.y;
        }
}

// ---------------- K5: cls/reg BN stats ----------------
__global__ void k5_stats2(const float* __restrict__ gc, const float* __restrict__ bc,
                          const float* __restrict__ gr, const float* __restrict__ br) {
    __shared__ float red[256];
    int b = blockIdx.x, tid = threadIdx.x;
    const float* src;
    int nch, ch;
    float gam, bet;
    if (b < NCLS) { src = sc_cls; nch = NCLS; ch = b; gam = gc[ch]; bet = bc[ch]; }
    else { src = sc_reg; nch = NREG; ch = b - NCLS; gam = gr[ch]; bet = br[ch]; }
    float s = 0.f;
    for (int n = 0; n < NB; n++) {
        const float* p = &src[(size_t)(n * nch + ch) * HWSZ];
        for (int i = tid; i < HWSZ; i += 256) s += p[i];
    }
    float mean = block_reduce(s, red, tid) * (1.f / (NB * HWSZ));
    s = 0.f;
    for (int n = 0; n < NB; n++) {
        const float* p = &src[(size_t)(n * nch + ch) * HWSZ];
        for (int i = tid; i < HWSZ; i += 256) {
            float d = p[i] - mean;
            s += d * d;
        }
    }
    float var = block_reduce(s, red, tid) * (1.f / (NB * HWSZ));
    if (tid == 0) {
        float inv = rsqrtf(var + BNEPS);
        float scl = gam * inv;
        sc_s2[b] = scl;
        sc_h2[b] = bet - mean * scl;
    }
}

// ---------------- K6: softmax + anchor decode ----------------
__constant__ float c_wa[9] = {455.f, 911.f, 1823.f, 319.f, 639.f, 1279.f, 223.f, 447.f, 895.f};
__constant__ float c_ha[9] = {223.f, 447.f, 895.f, 319.f, 639.f, 1279.f, 447.f, 895.f, 1791.f};

__global__ void k6_decode(const int* __restrict__ imgsz, float* __restrict__ out) {
    int t = blockIdx.x * 256 + threadIdx.x;
    if (t >= NB * HWSZ) return;
    int n = t >> 14, hw = t & 16383;
    int hy = hw >> 7, wx = hw & 127;
    float lim = 2048.f;
    if (imgsz) {
        int iv = *imgsz;
        lim = (iv > 0 && iv < (1 << 24)) ? (float)iv : __int_as_float(iv);
    }
    float cls[NCLS], rg[NREG];
#pragma unroll
    for (int o = 0; o < NCLS; o++)
        cls[o] = sc_cls[(size_t)(n * NCLS + o) * HWSZ + hw] * sc_s2[o] + sc_h2[o];
#pragma unroll
    for (int o = 0; o < NREG; o++)
        rg[o] = sc_reg[(size_t)(n * NREG + o) * HWSZ + hw] * sc_s2[NCLS + o] + sc_h2[NCLS + o];

    const size_t K = (size_t)HWSZ * 9;
    float* fg = out;
    float* ts = out + (size_t)NB * K;
    float* ro = ts + (size_t)NB * K * 4;
    size_t kb = (size_t)n * K + (size_t)hw * 9;

    float cxa = 19.5f + 16.f * (float)wx;
    float cya = 19.5f + 16.f * (float)hy;
#pragma unroll
    for (int a = 0; a < 9; a++) {
        float wa = c_wa[a], ha = c_ha[a];
        float x1 = fminf(fmaxf(rg[a * 4 + 0] + (cxa - 0.5f * wa), 0.f), lim);
        float y1 = fminf(fmaxf(rg[a * 4 + 1] + (cya - 0.5f * ha), 0.f), lim);
        float x2 = fminf(fmaxf(rg[a * 4 + 2] + (cxa + 0.5f * wa), 0.f), lim);
        float y2 = fminf(fmaxf(rg[a * 4 + 3] + (cya + 0.5f * ha), 0.f), lim);
        float w = x2 - x1, h = y2 - y1;
        float cx = x1 + 0.5f * w, cy = y1 + 0.5f * h;
        float s0 = cls[a * 2], s1 = cls[a * 2 + 1];
        fg[kb + a] = 1.f / (1.f + expf(s0 - s1));
        size_t o4 = (kb + a) * 4;
        ts[o4 + 0] = (cx - cxa) / wa;
        ts[o4 + 1] = (cy - cya) / ha;
        ts[o4 + 2] = logf(fmaxf(w / wa, 1e-30f));
        ts[o4 + 3] = logf(fmaxf(h / ha, 1e-30f));
        ro[o4 + 0] = cx;
        ro[o4 + 1] = cy;
        ro[o4 + 2] = w;
        ro[o4 + 3] = h;
    }
}

// ---------------- launch ----------------
extern "C" void kernel_launch(void* const* d_in, const int* in_sizes, int n_in,
                              void* d_out, int out_size) {
    const float* x   = (const float*)d_in[0];
    const float* Wb  = (const float*)d_in[1];
    const float* bb  = (const float*)d_in[2];
    const float* gb  = (const float*)d_in[3];
    const float* beb = (const float*)d_in[4];
    const float* Wc  = (const float*)d_in[5];
    const float* bc  = (const float*)d_in[6];
    const float* gc  = (const float*)d_in[7];
    const float* bec = (const float*)d_in[8];
    const float* Wr  = (const float*)d_in[9];
    const float* br  = (const float*)d_in[10];
    const float* gr  = (const float*)d_in[11];
    const float* ber = (const float*)d_in[12];
    const int* imgsz = (n_in > 13) ? (const int*)d_in[13] : nullptr;
    float* out = (float*)d_out;

    static int smem_set = 0;
    if (!smem_set) {
        cudaFuncSetAttribute(kconv, cudaFuncAttributeMaxDynamicSharedMemorySize, CONV_SMEM);
        cudaFuncSetAttribute(k4m, cudaFuncAttributeMaxDynamicSharedMemorySize, K4_SMEM);
        smem_set = 1;
    }

    dim3 gp(4, 128, NB);
    kP<<<gp, 256>>>(x);
    kW<<<9 * OCB, 256>>>(Wb);

    dim3 gc2(512, 2);
    kconv<<<gc2, 256, CONV_SMEM>>>(bb);

    k2_base_stats<<<OCB, 256>>>(gb, beb);
    k3_fold<<<NTOT, 256>>>(Wc, bc, Wr, br);

    k4m<<<NB * HWSZ / 512, 256, K4_SMEM>>>();

    k5_stats2<<<NTOT, 256>>>(gc, bec, gr, ber);
    k6_decode<<<NB * HWSZ / 256, 256>>>(imgsz, out);
}

// round 8
// speedup vs baseline: 3.4756x; 1.3565x over previous
#include <cuda_runtime.h>
#include <cuda_fp16.h>
#include <cstdint>
#include <math.h>

#define NB 8
#define CIN 256
#define HH 128
#define WW 128
#define HWSZ 16384
#define OCB 256
#define NCLS 18
#define NREG 36
#define NTOT 54
#define BNEPS 1e-5f
#define PW 130          // padded H/W

// ---------------- scratch (device globals; zero-initialized at load) ----------------
__device__ __half sc_pad[(size_t)NB * PW * PW * CIN];  // padded NHWC input, fp16, k-permuted (halo stays 0)
__device__ __half sc_Wp[9 * OCB * CIN];                // weights [tap][oc][ci], fp16, k-permuted
__device__ float sc_base[(size_t)NB * OCB * HWSZ];     // conv3x3+mish output (pre-BN), NCHW
__device__ float sc_part[256][512][2];                 // per-CTA (sum, sumsq) partials per channel
__device__ float sc_cls[(size_t)NB * NCLS * HWSZ];
__device__ float sc_reg[(size_t)NB * NREG * HWSZ];
__device__ float sc_scaleA[CIN];
__device__ float sc_shiftA[CIN];
__device__ float sc_Wf[NTOT * CIN];
__device__ float sc_bf[NTOT];
__device__ float sc_s2[NTOT];
__device__ float sc_h2[NTOT];

// ---------------- helpers ----------------
__device__ __forceinline__ void cpa16(void* dst, const void* src) {
    uint32_t d = (uint32_t)__cvta_generic_to_shared(dst);
    asm volatile("cp.async.cg.shared.global [%0], [%1], 16;" :: "r"(d), "l"(src));
}
__device__ __forceinline__ unsigned long long pk2(float v) {
    unsigned long long r; unsigned u = __float_as_uint(v);
    asm("mov.b64 %0, {%1, %2};" : "=l"(r) : "r"(u), "r"(u));
    return r;
}
__device__ __forceinline__ unsigned long long pk2ab(float a, float b) {
    unsigned long long r;
    asm("mov.b64 %0, {%1, %2};" : "=l"(r) : "r"(__float_as_uint(a)), "r"(__float_as_uint(b)));
    return r;
}
__device__ __forceinline__ void fma2(unsigned long long& d, unsigned long long a, unsigned long long b) {
    asm("fma.rn.f32x2 %0, %1, %2, %0;" : "+l"(d) : "l"(a), "l"(b));
}
__device__ __forceinline__ float2 upk(unsigned long long v) {
    unsigned lo, hi;
    asm("mov.b64 {%0, %1}, %2;" : "=r"(lo), "=r"(hi) : "l"(v));
    return make_float2(__uint_as_float(lo), __uint_as_float(hi));
}
__device__ __forceinline__ float mishf(float v) {
    float sp = fmaxf(v, 0.f) + log1pf(expf(-fabsf(v)));
    return v * tanhf(sp);
}
__device__ __forceinline__ float block_reduce(float v, float* red, int tid) {
    red[tid] = v; __syncthreads();
#pragma unroll
    for (int o = 128; o > 0; o >>= 1) {
        if (tid < o) red[tid] += red[tid + o];
        __syncthreads();
    }
    float r = red[0];
    __syncthreads();
    return r;
}
// within-16 permutation for m16n8k16 frags: place (2kc,2kc+1,2kc+8,2kc+9) contiguous per kc
__device__ __forceinline__ int pidx16(int k) {
    return (k < 8) ? ((k >> 1) * 4 + (k & 1)) : (((k - 8) >> 1) * 4 + 2 + (k & 1));
}
__device__ __forceinline__ int pidx32h(int a) {
    return (a & 16) + pidx16(a & 15);
}

// ---------------- kP: NCHW -> padded NHWC (fp16, k-permuted) ----------------
__global__ void kP(const float* __restrict__ x) {
    __shared__ float t[32][33];
    int n = blockIdx.z, h = blockIdx.y, w0 = blockIdx.x * 32;
    int tid = threadIdx.x;
    int a = tid & 31, b = tid >> 5;  // b: 0..7
    int pa = pidx32h(a);
    for (int c0 = 0; c0 < CIN; c0 += 32) {
        __syncthreads();
#pragma unroll
        for (int j = 0; j < 4; j++) {
            int c = c0 + b + j * 8;
            t[b + j * 8][a] = x[(((size_t)n * CIN + c) * HH + h) * WW + w0 + a];
        }
        __syncthreads();
#pragma unroll
        for (int j = 0; j < 4; j++) {
            int w = w0 + b + j * 8;
            sc_pad[(((size_t)n * PW + (h + 1)) * PW + (w + 1)) * CIN + c0 + pa] =
                __float2half_rn(t[a][b + j * 8]);
        }
    }
}

// ---------------- kW: W[oc][ci][3][3] -> Wp[tap][oc][ci] (fp16, k-permuted) ----------------
__global__ void kW(const float* __restrict__ W) {
    int bi = blockIdx.x;            // 0..2303
    int oc = bi & 255, tap = bi >> 8;
    int ci = threadIdx.x;
    int pci = (ci & ~31) | pidx32h(ci & 31);
    sc_Wp[((size_t)tap * OCB + oc) * CIN + pci] =
        __float2half_rn(W[((size_t)oc * CIN + ci) * 9 + tap]);
}

// ---------------- kconv: fp16 mma.sync m16n8k16 implicit GEMM, triple-buffered ----------------
// CTA: 256 thr, 8 warps (wm 0..3 x wn 0..1). Tile M=256 (2 image rows) x N=128.
// Stage (24 = 3 dy x 8 ci-chunks of 32): A[260 pos][40h], B[3 dx][128 oc][40h]
#define AFH 10400
#define BFH 15360
#define B0H 31200
#define CONV_SMEM ((B0H + 3 * BFH) * 2)   // 154560 B

__device__ __forceinline__ void issue_stage(const __half* __restrict__ pad_n, int by, int h0,
                                            int stage, __half* sm, int buf, int tid) {
    int dy = stage >> 3, chunk = stage & 7;
    __half* A = sm + buf * AFH;
    __half* B = sm + B0H + buf * BFH;
    for (int i = tid; i < 1040; i += 256) {
        int pos = i >> 2, q = i & 3;
        int r = pos / 130, j = pos - r * 130;
        const __half* src = pad_n + ((size_t)(h0 + r + dy) * PW + j) * CIN + chunk * 32 + q * 8;
        cpa16(A + pos * 40 + q * 8, src);
    }
    for (int i = tid; i < 1536; i += 256) {
        int dx = i >> 9, rem = i & 511;
        int ocl = rem >> 2, q = rem & 3;
        const __half* src = sc_Wp + ((size_t)((dy * 3 + dx) * OCB + by * 128 + ocl)) * CIN
                            + chunk * 32 + q * 8;
        cpa16(B + dx * 5120 + ocl * 40 + q * 8, src);
    }
    asm volatile("cp.async.commit_group;" ::: "memory");
}

__global__ void __launch_bounds__(256, 1) kconv(const float* __restrict__ pb) {
    extern __shared__ __half smh[];
    int tid = threadIdx.x, lane = tid & 31;
    int wid = tid >> 5;
    int wm = wid & 3, wn = wid >> 2;
    int s = blockIdx.x;
    int n = s >> 6, h0 = (s & 63) * 2;
    int by = blockIdx.y;
    const __half* pad_n = sc_pad + (size_t)n * PW * PW * CIN;

    float acc[4][8][4];
#pragma unroll
    for (int a = 0; a < 4; a++)
#pragma unroll
        for (int b = 0; b < 8; b++)
#pragma unroll
            for (int c = 0; c < 4; c++) acc[a][b][c] = 0.f;

    int mrow = lane >> 2, kc = lane & 3;
    int wbase = (wm >> 1) * 130 + (wm & 1) * 64;
    int ocl0 = wn * 64 + mrow;

    issue_stage(pad_n, by, h0, 0, smh, 0, tid);
    issue_stage(pad_n, by, h0, 1, smh, 1, tid);

    int buf = 0, nbuf = 2;   // ring indices (avoid div/mod in hot loop)
#pragma unroll 1
    for (int st = 0; st < 24; st++) {
        if (st + 2 < 24) {
            issue_stage(pad_n, by, h0, st + 2, smh, nbuf, tid);
            if (++nbuf == 3) nbuf = 0;
            asm volatile("cp.async.wait_group 2;" ::: "memory");
        } else if (st + 1 < 24) {
            asm volatile("cp.async.wait_group 1;" ::: "memory");
        } else {
            asm volatile("cp.async.wait_group 0;" ::: "memory");
        }
        __syncthreads();

        const __half* A = smh + buf * AFH;
        const __half* B = smh + B0H + buf * BFH;
        if (++buf == 3) buf = 0;
#pragma unroll
        for (int dx = 0; dx < 3; dx++) {
#pragma unroll
            for (int ks = 0; ks < 2; ks++) {
                uint32_t af[4][4];
#pragma unroll
                for (int mf = 0; mf < 4; mf++) {
                    const uint2* plo = (const uint2*)(A + (wbase + mf * 16 + mrow + dx) * 40
                                                     + ks * 16 + kc * 4);
                    const uint2* phi = (const uint2*)((const __half*)plo + 320);  // row+8
                    uint2 lo = *plo, hi = *phi;
                    af[mf][0] = lo.x;   // (r,   2kc..2kc+1)
                    af[mf][1] = hi.x;   // (r+8, 2kc..2kc+1)
                    af[mf][2] = lo.y;   // (r,   2kc+8..9)
                    af[mf][3] = hi.y;   // (r+8, 2kc+8..9)
                }
                uint32_t bfr[8][2];
#pragma unroll
                for (int nf = 0; nf < 8; nf++) {
                    uint2 bv = *(const uint2*)(B + dx * 5120 + (ocl0 + nf * 8) * 40
                                               + ks * 16 + kc * 4);
                    bfr[nf][0] = bv.x;
                    bfr[nf][1] = bv.y;
                }
#pragma unroll
                for (int mf = 0; mf < 4; mf++)
#pragma unroll
                    for (int nf = 0; nf < 8; nf++)
                        asm volatile(
                            "mma.sync.aligned.m16n8k16.row.col.f32.f16.f16.f32 "
                            "{%0,%1,%2,%3}, {%4,%5,%6,%7}, {%8,%9}, {%0,%1,%2,%3};"
                            : "+f"(acc[mf][nf][0]), "+f"(acc[mf][nf][1]),
                              "+f"(acc[mf][nf][2]), "+f"(acc[mf][nf][3])
                            : "r"(af[mf][0]), "r"(af[mf][1]), "r"(af[mf][2]), "r"(af[mf][3]),
                              "r"(bfr[nf][0]), "r"(bfr[nf][1]));
            }
        }
        __syncthreads();
    }

    // epilogue: bias + mish -> sc_base NCHW, plus deterministic per-channel stats partials
    int h = h0 + (wm >> 1);
    float ssum[8][2], ssq[8][2];
#pragma unroll
    for (int nf = 0; nf < 8; nf++) {
        ssum[nf][0] = ssum[nf][1] = 0.f;
        ssq[nf][0] = ssq[nf][1] = 0.f;
    }
#pragma unroll
    for (int mf = 0; mf < 4; mf++) {
        int w = (wm & 1) * 64 + mf * 16 + mrow;
#pragma unroll
        for (int nf = 0; nf < 8; nf++) {
            int oc = by * 128 + wn * 64 + nf * 8 + 2 * kc;
            float b0v = pb[oc], b1v = pb[oc + 1];
            float v0 = mishf(acc[mf][nf][0] + b0v);
            float v1 = mishf(acc[mf][nf][1] + b1v);
            float v2 = mishf(acc[mf][nf][2] + b0v);
            float v3 = mishf(acc[mf][nf][3] + b1v);
            float* p = sc_base + ((size_t)(n * OCB + oc)) * HWSZ + h * WW + w;
            p[0] = v0; p[HWSZ] = v1; p[8] = v2; p[HWSZ + 8] = v3;
            ssum[nf][0] += v0 + v2;  ssq[nf][0] += v0 * v0 + v2 * v2;
            ssum[nf][1] += v1 + v3;  ssq[nf][1] += v1 * v1 + v3 * v3;
        }
    }
#pragma unroll
    for (int off = 4; off <= 16; off <<= 1) {
#pragma unroll
        for (int nf = 0; nf < 8; nf++)
#pragma unroll
            for (int j = 0; j < 2; j++) {
                ssum[nf][j] += __shfl_xor_sync(0xffffffffu, ssum[nf][j], off);
                ssq[nf][j] += __shfl_xor_sync(0xffffffffu, ssq[nf][j], off);
            }
    }
    float* part = (float*)smh;  // overlay [wn][wm][64 chl][2]
    if (mrow == 0) {
#pragma unroll
        for (int nf = 0; nf < 8; nf++)
#pragma unroll
            for (int j = 0; j < 2; j++) {
                int chl = nf * 8 + 2 * kc + j;
                part[((wn * 4 + wm) * 64 + chl) * 2 + 0] = ssum[nf][j];
                part[((wn * 4 + wm) * 64 + chl) * 2 + 1] = ssq[nf][j];
            }
    }
    __syncthreads();
    {
        int wn2 = tid >> 7, chl = (tid >> 1) & 63, v = tid & 1;
        float t = 0.f;
#pragma unroll
        for (int wm2 = 0; wm2 < 4; wm2++)
            t += part[((wn2 * 4 + wm2) * 64 + chl) * 2 + v];
        sc_part[by * 128 + wn2 * 64 + chl][s][v] = t;
    }
}

// ---------------- K2: base BN stats from partials (deterministic fixed-order) ----------------
__global__ void k2_base_stats(const float* __restrict__ gam, const float* __restrict__ bet) {
    __shared__ float red[256];
    int c = blockIdx.x, tid = threadIdx.x;
    float s = sc_part[c][tid][0] + sc_part[c][tid + 256][0];
    float sum = block_reduce(s, red, tid);
    float q = sc_part[c][tid][1] + sc_part[c][tid + 256][1];
    float sq = block_reduce(q, red, tid);
    if (tid == 0) {
        float inv_n = 1.f / (float)(NB * HWSZ);
        float mean = sum * inv_n;
        float var = sq * inv_n - mean * mean;
        float inv = rsqrtf(var + BNEPS);
        float scl = gam[c] * inv;
        sc_scaleA[c] = scl;
        sc_shiftA[c] = bet[c] - mean * scl;
    }
}

// ---------------- K3: fold base BN into 1x1 conv weights ----------------
__global__ void k3_fold(const float* __restrict__ Wc, const float* __restrict__ bc,
                        const float* __restrict__ Wr, const float* __restrict__ br) {
    __shared__ float red[256];
    int o = blockIdx.x, ci = threadIdx.x;
    const float* Ws;
    float bs;
    int ol;
    if (o < NCLS) { Ws = Wc; ol = o; bs = bc[o]; }
    else { Ws = Wr; ol = o - NCLS; bs = br[ol]; }
    float w = Ws[ol * CIN + ci];
    sc_Wf[o * CIN + ci] = w * sc_scaleA[ci];
    float tot = block_reduce(w * sc_shiftA[ci], red, ci);
    if (ci == 0) sc_bf[o] = bs + tot;
}

// ---------------- K4m: merged 1x1 convs (cls+reg), f32x2 packed, single read of sc_base ----------------
#define K4_SMEM (CIN * 56 * 4)
__global__ void __launch_bounds__(256) k4m() {
    extern __shared__ float swf[];  // [c][56]
    int tid = threadIdx.x;
    for (int i = tid; i < CIN * 56; i += 256) {
        int c = i / 56, o = i - c * 56;
        swf[i] = (o < NTOT) ? sc_Wf[o * CIN + c] : 0.f;
    }
    __syncthreads();
    int pstart = blockIdx.x * 512;     // 256 thr x 2 px
    int n = pstart >> 14;
    int hwb = (pstart & 16383) + tid;  // px at hwb, hwb+256

    unsigned long long acc2[27][2];
#pragma unroll
    for (int op = 0; op < 27; op++) {
        unsigned long long b = pk2ab(sc_bf[2 * op], sc_bf[2 * op + 1]);
        acc2[op][0] = b;
        acc2[op][1] = b;
    }
    const float* bpn = sc_base + (size_t)n * OCB * HWSZ + hwb;
#pragma unroll 1
    for (int c = 0; c < CIN; c += 8) {
        float v0[8], v1[8];
#pragma unroll
        for (int u = 0; u < 8; u++) {
            const float* p = bpn + (size_t)(c + u) * HWSZ;
            v0[u] = p[0];
            v1[u] = p[256];
        }
#pragma unroll
        for (int u = 0; u < 8; u++) {
            unsigned long long p0 = pk2(v0[u]), p1 = pk2(v1[u]);
            const unsigned long long* wrow = (const unsigned long long*)(swf + (c + u) * 56);
#pragma unroll
            for (int op = 0; op < 27; op++) {
                unsigned long long w = wrow[op];
                fma2(acc2[op][0], w, p0);
                fma2(acc2[op][1], w, p1);
            }
        }
    }
#pragma unroll
    for (int op = 0; op < 27; op++)
#pragma unroll
        for (int px = 0; px < 2; px++) {
            float2 u = upk(acc2[op][px]);
            int ch0 = 2 * op, ch1 = 2 * op + 1;
            size_t idx = hwb + px * 256;
            if (ch0 < NCLS) sc_cls[(size_t)(n * NCLS + ch0) * HWSZ + idx] = u.x;
            else sc_reg[(size_t)(n * NREG + (ch0 - NCLS)) * HWSZ + idx] = u.x;
            if (ch1 < NCLS) sc_cls[(size_t)(n * NCLS + ch1) * HWSZ + idx] = u.y;
            else sc_reg[(size_t)(n * NREG + (ch1 - NCLS)) * HWSZ + idx] = u.y;
        }
}

// ---------------- K5: cls/reg BN stats ----------------
__global__ void k5_stats2(const float* __restrict__ gc, const float* __restrict__ bc,
                          const float* __restrict__ gr, const float* __restrict__ br) {
    __shared__ float red[256];
    int b = blockIdx.x, tid = threadIdx.x;
    const float* src;
    int nch, ch;
    float gam, bet;
    if (b < NCLS) { src = sc_cls; nch = NCLS; ch = b; gam = gc[ch]; bet = bc[ch]; }
    else { src = sc_reg; nch = NREG; ch = b - NCLS; gam = gr[ch]; bet = br[ch]; }
    float s = 0.f;
    for (int n = 0; n < NB; n++) {
        const float* p = &src[(size_t)(n * nch + ch) * HWSZ];
        for (int i = tid; i < HWSZ; i += 256) s += p[i];
    }
    float mean = block_reduce(s, red, tid) * (1.f / (NB * HWSZ));
    s = 0.f;
    for (int n = 0; n < NB; n++) {
        const float* p = &src[(size_t)(n * nch + ch) * HWSZ];
        for (int i = tid; i < HWSZ; i += 256) {
            float d = p[i] - mean;
            s += d * d;
        }
    }
    float var = block_reduce(s, red, tid) * (1.f / (NB * HWSZ));
    if (tid == 0) {
        float inv = rsqrtf(var + BNEPS);
        float scl = gam * inv;
        sc_s2[b] = scl;
        sc_h2[b] = bet - mean * scl;
    }
}

// ---------------- K6: softmax + anchor decode ----------------
__constant__ float c_wa[9] = {455.f, 911.f, 1823.f, 319.f, 639.f, 1279.f, 223.f, 447.f, 895.f};
__constant__ float c_ha[9] = {223.f, 447.f, 895.f, 319.f, 639.f, 1279.f, 447.f, 895.f, 1791.f};

__global__ void k6_decode(const int* __restrict__ imgsz, float* __restrict__ out) {
    int t = blockIdx.x * 256 + threadIdx.x;
    if (t >= NB * HWSZ) return;
    int n = t >> 14, hw = t & 16383;
    int hy = hw >> 7, wx = hw & 127;
    float lim = 2048.f;
    if (imgsz) {
        int iv = *imgsz;
        lim = (iv > 0 && iv < (1 << 24)) ? (float)iv : __int_as_float(iv);
    }
    float cls[NCLS], rg[NREG];
#pragma unroll
    for (int o = 0; o < NCLS; o++)
        cls[o] = sc_cls[(size_t)(n * NCLS + o) * HWSZ + hw] * sc_s2[o] + sc_h2[o];
#pragma unroll
    for (int o = 0; o < NREG; o++)
        rg[o] = sc_reg[(size_t)(n * NREG + o) * HWSZ + hw] * sc_s2[NCLS + o] + sc_h2[NCLS + o];

    const size_t K = (size_t)HWSZ * 9;
    float* fg = out;
    float* ts = out + (size_t)NB * K;
    float* ro = ts + (size_t)NB * K * 4;
    size_t kb = (size_t)n * K + (size_t)hw * 9;

    float cxa = 19.5f + 16.f * (float)wx;
    float cya = 19.5f + 16.f * (float)hy;
#pragma unroll
    for (int a = 0; a < 9; a++) {
        float wa = c_wa[a], ha = c_ha[a];
        float x1 = fminf(fmaxf(rg[a * 4 + 0] + (cxa - 0.5f * wa), 0.f), lim);
        float y1 = fminf(fmaxf(rg[a * 4 + 1] + (cya - 0.5f * ha), 0.f), lim);
        float x2 = fminf(fmaxf(rg[a * 4 + 2] + (cxa + 0.5f * wa), 0.f), lim);
        float y2 = fminf(fmaxf(rg[a * 4 + 3] + (cya + 0.5f * ha), 0.f), lim);
        float w = x2 - x1, h = y2 - y1;
        float cx = x1 + 0.5f * w, cy = y1 + 0.5f * h;
        float s0 = cls[a * 2], s1 = cls[a * 2 + 1];
        fg[kb + a] = 1.f / (1.f + expf(s0 - s1));
        size_t o4 = (kb + a) * 4;
        ts[o4 + 0] = (cx - cxa) / wa;
        ts[o4 + 1] = (cy - cya) / ha;
        ts[o4 + 2] = logf(fmaxf(w / wa, 1e-30f));
        ts[o4 + 3] = logf(fmaxf(h / ha, 1e-30f));
        ro[o4 + 0] = cx;
        ro[o4 + 1] = cy;
        ro[o4 + 2] = w;
        ro[o4 + 3] = h;
    }
}

// ---------------- launch ----------------
extern "C" void kernel_launch(void* const* d_in, const int* in_sizes, int n_in,
                              void* d_out, int out_size) {
    const float* x   = (const float*)d_in[0];
    const float* Wb  = (const float*)d_in[1];
    const float* bb  = (const float*)d_in[2];
    const float* gb  = (const float*)d_in[3];
    const float* beb = (const float*)d_in[4];
    const float* Wc  = (const float*)d_in[5];
    const float* bc  = (const float*)d_in[6];
    const float* gc  = (const float*)d_in[7];
    const float* bec = (const float*)d_in[8];
    const float* Wr  = (const float*)d_in[9];
    const float* br  = (const float*)d_in[10];
    const float* gr  = (const float*)d_in[11];
    const float* ber = (const float*)d_in[12];
    const int* imgsz = (n_in > 13) ? (const int*)d_in[13] : nullptr;
    float* out = (float*)d_out;

    static int smem_set = 0;
    if (!smem_set) {
        cudaFuncSetAttribute(kconv, cudaFuncAttributeMaxDynamicSharedMemorySize, CONV_SMEM);
        cudaFuncSetAttribute(k4m, cudaFuncAttributeMaxDynamicSharedMemorySize, K4_SMEM);
        smem_set = 1;
    }

    dim3 gp(4, 128, NB);
    kP<<<gp, 256>>>(x);
    kW<<<9 * OCB, 256>>>(Wb);

    dim3 gc2(512, 2);
    kconv<<<gc2, 256, CONV_SMEM>>>(bb);

    k2_base_stats<<<OCB, 256>>>(gb, beb);
    k3_fold<<<NTOT, 256>>>(Wc, bc, Wr, br);

    k4m<<<NB * HWSZ / 512, 256, K4_SMEM>>>();

    k5_stats2<<<NTOT, 256>>>(gc, bec, gr, ber);
    k6_decode<<<NB * HWSZ / 256, 256>>>(imgsz, out);
}

// round 9
// speedup vs baseline: 3.6538x; 1.0513x over previous
#include <cuda_runtime.h>
#include <cuda_fp16.h>
#include <cstdint>
#include <math.h>

#define NB 8
#define CIN 256
#define HH 128
#define WW 128
#define HWSZ 16384
#define OCB 256
#define NCLS 18
#define NREG 36
#define NTOT 54
#define BNEPS 1e-5f
#define PW 130          // padded H/W

// ---------------- scratch (device globals; zero-initialized at load) ----------------
// chunk-major padded input: [n][chunk 8][h 130][w 130][32 ci as 8B-units e'=swizzled]
__device__ __half sc_pad[(size_t)NB * 8 * PW * PW * 32];
// weights: [chunk 8][tap 9][oc 256][32 ci swizzled]
__device__ __half sc_Wp[8 * 9 * OCB * 32];
__device__ float sc_base[(size_t)NB * OCB * HWSZ];     // conv3x3+mish output (pre-BN), NCHW
__device__ float sc_part[256][512][2];                 // per-CTA (sum, sumsq) partials per channel
__device__ float sc_cls[(size_t)NB * NCLS * HWSZ];
__device__ float sc_reg[(size_t)NB * NREG * HWSZ];
__device__ float sc_scaleA[CIN];
__device__ float sc_shiftA[CIN];
__device__ float sc_Wf[NTOT * CIN];
__device__ float sc_bf[NTOT];
__device__ float sc_s2[NTOT];
__device__ float sc_h2[NTOT];

// ---------------- helpers ----------------
__device__ __forceinline__ uint32_t smem_u32(const void* p) {
    return (uint32_t)__cvta_generic_to_shared(p);
}
__device__ __forceinline__ unsigned long long pk2(float v) {
    unsigned long long r; unsigned u = __float_as_uint(v);
    asm("mov.b64 %0, {%1, %2};" : "=l"(r) : "r"(u), "r"(u));
    return r;
}
__device__ __forceinline__ unsigned long long pk2ab(float a, float b) {
    unsigned long long r;
    asm("mov.b64 %0, {%1, %2};" : "=l"(r) : "r"(__float_as_uint(a)), "r"(__float_as_uint(b)));
    return r;
}
__device__ __forceinline__ void fma2(unsigned long long& d, unsigned long long a, unsigned long long b) {
    asm("fma.rn.f32x2 %0, %1, %2, %0;" : "+l"(d) : "l"(a), "l"(b));
}
__device__ __forceinline__ float2 upk(unsigned long long v) {
    unsigned lo, hi;
    asm("mov.b64 {%0, %1}, %2;" : "=r"(lo), "=r"(hi) : "l"(v));
    return make_float2(__uint_as_float(lo), __uint_as_float(hi));
}
__device__ __forceinline__ float mishf(float v) {
    float sp = fmaxf(v, 0.f) + log1pf(expf(-fabsf(v)));
    return v * tanhf(sp);
}
__device__ __forceinline__ float block_reduce(float v, float* red, int tid) {
    red[tid] = v; __syncthreads();
#pragma unroll
    for (int o = 128; o > 0; o >>= 1) {
        if (tid < o) red[tid] += red[tid + o];
        __syncthreads();
    }
    float r = red[0];
    __syncthreads();
    return r;
}
// within-16 permutation for m16n8k16 frags: (2kc,2kc+1,2kc+8,2kc+9) contiguous per kc
__device__ __forceinline__ int pidx16(int k) {
    return (k < 8) ? ((k >> 1) * 4 + (k & 1)) : (((k - 8) >> 1) * 4 + 2 + (k & 1));
}
__device__ __forceinline__ int pidx32h(int a) {
    return (a & 16) + pidx16(a & 15);
}
// bank swizzle of 8B-unit index by row index p (conflict-free frag loads)
__device__ __forceinline__ int swz(int p) {
    int t = (p >> 1) & 3;
    return t ^ ((t & 1) << 2);
}

#define MBAR_INIT(a, c) \
    asm volatile("mbarrier.init.shared.b64 [%0], %1;" :: "r"((uint32_t)(a)), "r"((uint32_t)(c)) : "memory")
#define MBAR_EXPECT(a, bytes) \
    asm volatile("mbarrier.arrive.expect_tx.shared.b64 _, [%0], %1;" :: "r"((uint32_t)(a)), "r"((uint32_t)(bytes)) : "memory")
#define MBAR_WAIT(a, p) do {                                                         \
    uint32_t _m = (uint32_t)(a), _p = (uint32_t)(p), _d;                             \
    asm volatile("{\n\t.reg .pred q;\n\t"                                            \
        "mbarrier.try_wait.parity.acquire.cta.shared::cta.b64 q, [%1], %2;\n\t"      \
        "selp.b32 %0, 1, 0, q;\n\t}" : "=r"(_d) : "r"(_m), "r"(_p) : "memory");      \
    if (!_d) {                                                                       \
        asm volatile("{\n\t.reg .pred Q;\n\tWL_%=:\n\t"                              \
            "mbarrier.try_wait.parity.acquire.cta.shared::cta.b64 Q, [%0], %1, 0x989680;\n\t" \
            "@Q bra.uni WD_%=;\n\tbra.uni WL_%=;\n\tWD_%=:\n\t}"                     \
            :: "r"(_m), "r"(_p) : "memory");                                         \
    }                                                                                \
} while (0)

__device__ __forceinline__ void bulk_cp(uint32_t dst, const void* src, uint32_t bytes, uint32_t mbar) {
    asm volatile(
        "cp.async.bulk.shared::cluster.global.mbarrier::complete_tx::bytes [%0], [%1], %2, [%3];"
        :: "r"(dst), "l"(src), "r"(bytes), "r"(mbar) : "memory");
}

// ---------------- kP: NCHW -> chunk-major padded fp16, k-permuted + bank-swizzled ----------------
__global__ void kP(const float* __restrict__ x) {
    __shared__ float t[32][33];
    int n = blockIdx.z, h = blockIdx.y, w0 = blockIdx.x * 32;
    int tid = threadIdx.x;
    int a = tid & 31, b = tid >> 5;  // b: 0..7
    int pc = pidx32h(a);
    int e = pc >> 2, hf = pc & 3;
    for (int c0 = 0; c0 < CIN; c0 += 32) {
        int ch = c0 >> 5;
        __syncthreads();
#pragma unroll
        for (int j = 0; j < 4; j++) {
            int c = c0 + b + j * 8;
            t[b + j * 8][a] = x[(((size_t)n * CIN + c) * HH + h) * WW + w0 + a];
        }
        __syncthreads();
#pragma unroll
        for (int j = 0; j < 4; j++) {
            int wp = w0 + b + j * 8 + 1;
            int ep = e ^ swz(wp);
            size_t idx = ((((size_t)n * 8 + ch) * PW + (h + 1)) * PW + wp) * 32 + ep * 4 + hf;
            sc_pad[idx] = __float2half_rn(t[a][b + j * 8]);
        }
    }
}

// ---------------- kW: W[oc][ci][3][3] -> Wp[chunk][tap][oc][swizzled 32] ----------------
__global__ void kW(const float* __restrict__ W) {
    int bi = blockIdx.x;            // 0..2303
    int oc = bi & 255, tap = bi >> 8;
    int ci = threadIdx.x;
    int ch = ci >> 5, c32 = ci & 31;
    int pc = pidx32h(c32);
    int ep = (pc >> 2) ^ swz(oc & 7);
    sc_Wp[(((size_t)ch * 9 + tap) * OCB + oc) * 32 + ep * 4 + (pc & 3)] =
        __float2half_rn(W[((size_t)oc * CIN + ci) * 9 + tap]);
}

// ---------------- kconv: fp16 m16n8k16, bulk-copy staged, conflict-free frags ----------------
// CTA: 256 thr, 8 warps (wm 0..3 x wn 0..1). Tile M=256 (2 out rows) x N=128 oc.
// Stage = one ci-chunk: A[4 rows][130][64B] (4x8320B) + B[9 taps][128 oc][64B] (9x8192B)
#define A_ROW_H   4160          // halves per A row (130*32)
#define A_H       16640         // halves per A tile (4 rows)
#define B_TAP_H   4096          // halves per B tap (128*32)
#define STAGE_H   53504         // halves per stage (A_H + 9*B_TAP_H)
#define STAGE_BYTES 107008u
#define MBAR_OFF  214016u
#define CONV_SMEM 214048

__device__ __forceinline__ void issue_bulk(const __half* __restrict__ padn,
                                           const __half* __restrict__ wpn,
                                           int h0, int by, int ch,
                                           uint32_t smbase, int buf, uint32_t mbar) {
    MBAR_EXPECT(mbar, STAGE_BYTES);
    uint32_t dst = smbase + (uint32_t)buf * STAGE_BYTES;
    const __half* asrc = padn + ((size_t)ch * PW + h0) * (PW * 32);
#pragma unroll
    for (int r = 0; r < 4; r++)
        bulk_cp(dst + r * 8320u, asrc + (size_t)r * A_ROW_H, 8320u, mbar);
    const __half* bsrc = wpn + (((size_t)ch * 9) * OCB + by * 128) * 32;
#pragma unroll
    for (int tp = 0; tp < 9; tp++)
        bulk_cp(dst + 33280u + tp * 8192u, bsrc + (size_t)tp * OCB * 32, 8192u, mbar);
}

__global__ void __launch_bounds__(256, 1) kconv(const float* __restrict__ pb) {
    extern __shared__ __half smh[];
    uint32_t smbase = smem_u32(smh);
    int tid = threadIdx.x, lane = tid & 31;
    int wid = tid >> 5;
    int wm = wid & 3, wn = wid >> 2;
    int s = blockIdx.x;
    int n = s >> 6, h0 = (s & 63) * 2;
    int by = blockIdx.y;
    const __half* padn = sc_pad + (size_t)n * 8 * PW * PW * 32;

    float acc[4][8][4];
#pragma unroll
    for (int a = 0; a < 4; a++)
#pragma unroll
        for (int b = 0; b < 8; b++)
#pragma unroll
            for (int c = 0; c < 4; c++) acc[a][b][c] = 0.f;

    int mrow = lane >> 2, kc = lane & 3;
    int ro = wm >> 1;                         // out-row offset 0..1
    int pbase = (wm & 1) * 64 + mrow;         // + mf*16 + dx
    int brow = wn * 64 + mrow;                // + nf*8
    int xB = swz(mrow);

    uint32_t mb0 = smbase + MBAR_OFF, mb1 = mb0 + 8;
    if (tid == 0) {
        MBAR_INIT(mb0, 1);
        MBAR_INIT(mb1, 1);
    }
    __syncthreads();
    if (tid == 0) {
        issue_bulk(padn, sc_Wp, h0, by, 0, smbase, 0, mb0);
        issue_bulk(padn, sc_Wp, h0, by, 1, smbase, 1, mb1);
    }

#pragma unroll 1
    for (int st = 0; st < 8; st++) {
        MBAR_WAIT(st & 1 ? mb1 : mb0, (st >> 1) & 1);

        const __half* A = smh + (st & 1) * STAGE_H;
        const __half* B = A + A_H;
#pragma unroll
        for (int dy = 0; dy < 3; dy++) {
            const __half* Arow = A + (ro + dy) * A_ROW_H;
#pragma unroll
            for (int dx = 0; dx < 3; dx++) {
                int xA = swz((mrow + dx) & 7);
                const __half* Bt = B + (dy * 3 + dx) * B_TAP_H;
#pragma unroll
                for (int ks = 0; ks < 2; ks++) {
                    int eA = ((ks * 4 + kc) ^ xA) * 4;
                    int eB = ((ks * 4 + kc) ^ xB) * 4;
                    uint32_t af[4][4];
#pragma unroll
                    for (int mf = 0; mf < 4; mf++) {
                        int p = pbase + mf * 16 + dx;
                        const uint2* plo = (const uint2*)(Arow + p * 32 + eA);
                        uint2 lo = plo[0];
                        uint2 hi = *(const uint2*)((const __half*)plo + 256);  // p+8
                        af[mf][0] = lo.x;
                        af[mf][1] = hi.x;
                        af[mf][2] = lo.y;
                        af[mf][3] = hi.y;
                    }
                    uint32_t bfr[8][2];
#pragma unroll
                    for (int nf = 0; nf < 8; nf++) {
                        uint2 bv = *(const uint2*)(Bt + (brow + nf * 8) * 32 + eB);
                        bfr[nf][0] = bv.x;
                        bfr[nf][1] = bv.y;
                    }
#pragma unroll
                    for (int mf = 0; mf < 4; mf++)
#pragma unroll
                        for (int nf = 0; nf < 8; nf++)
                            asm volatile(
                                "mma.sync.aligned.m16n8k16.row.col.f32.f16.f16.f32 "
                                "{%0,%1,%2,%3}, {%4,%5,%6,%7}, {%8,%9}, {%0,%1,%2,%3};"
                                : "+f"(acc[mf][nf][0]), "+f"(acc[mf][nf][1]),
                                  "+f"(acc[mf][nf][2]), "+f"(acc[mf][nf][3])
                                : "r"(af[mf][0]), "r"(af[mf][1]), "r"(af[mf][2]), "r"(af[mf][3]),
                                  "r"(bfr[nf][0]), "r"(bfr[nf][1]));
                }
            }
        }
        __syncthreads();
        if (st + 2 < 8 && tid == 0)
            issue_bulk(padn, sc_Wp, h0, by, st + 2, smbase, st & 1, st & 1 ? mb1 : mb0);
    }

    // epilogue: bias + mish -> sc_base NCHW, plus deterministic per-channel stats partials
    int h = h0 + ro;
    float ssum[8][2], ssq[8][2];
#pragma unroll
    for (int nf = 0; nf < 8; nf++) {
        ssum[nf][0] = ssum[nf][1] = 0.f;
        ssq[nf][0] = ssq[nf][1] = 0.f;
    }
#pragma unroll
    for (int mf = 0; mf < 4; mf++) {
        int w = (wm & 1) * 64 + mf * 16 + mrow;
#pragma unroll
        for (int nf = 0; nf < 8; nf++) {
            int oc = by * 128 + wn * 64 + nf * 8 + 2 * kc;
            float b0v = pb[oc], b1v = pb[oc + 1];
            float v0 = mishf(acc[mf][nf][0] + b0v);
            float v1 = mishf(acc[mf][nf][1] + b1v);
            float v2 = mishf(acc[mf][nf][2] + b0v);
            float v3 = mishf(acc[mf][nf][3] + b1v);
            float* p = sc_base + ((size_t)(n * OCB + oc)) * HWSZ + h * WW + w;
            p[0] = v0; p[HWSZ] = v1; p[8] = v2; p[HWSZ + 8] = v3;
            ssum[nf][0] += v0 + v2;  ssq[nf][0] += v0 * v0 + v2 * v2;
            ssum[nf][1] += v1 + v3;  ssq[nf][1] += v1 * v1 + v3 * v3;
        }
    }
#pragma unroll
    for (int off = 4; off <= 16; off <<= 1) {
#pragma unroll
        for (int nf = 0; nf < 8; nf++)
#pragma unroll
            for (int j = 0; j < 2; j++) {
                ssum[nf][j] += __shfl_xor_sync(0xffffffffu, ssum[nf][j], off);
                ssq[nf][j] += __shfl_xor_sync(0xffffffffu, ssq[nf][j], off);
            }
    }
    float* part = (float*)smh;  // overlay [wn][wm][64 chl][2]
    __syncthreads();
    if (mrow == 0) {
#pragma unroll
        for (int nf = 0; nf < 8; nf++)
#pragma unroll
            for (int j = 0; j < 2; j++) {
                int chl = nf * 8 + 2 * kc + j;
                part[((wn * 4 + wm) * 64 + chl) * 2 + 0] = ssum[nf][j];
                part[((wn * 4 + wm) * 64 + chl) * 2 + 1] = ssq[nf][j];
            }
    }
    __syncthreads();
    {
        int wn2 = tid >> 7, chl = (tid >> 1) & 63, v = tid & 1;
        float t = 0.f;
#pragma unroll
        for (int wm2 = 0; wm2 < 4; wm2++)
            t += part[((wn2 * 4 + wm2) * 64 + chl) * 2 + v];
        sc_part[by * 128 + wn2 * 64 + chl][s][v] = t;
    }
}

// ---------------- K2: base BN stats from partials (deterministic fixed-order) ----------------
__global__ void k2_base_stats(const float* __restrict__ gam, const float* __restrict__ bet) {
    __shared__ float red[256];
    int c = blockIdx.x, tid = threadIdx.x;
    float s = sc_part[c][tid][0] + sc_part[c][tid + 256][0];
    float sum = block_reduce(s, red, tid);
    float q = sc_part[c][tid][1] + sc_part[c][tid + 256][1];
    float sq = block_reduce(q, red, tid);
    if (tid == 0) {
        float inv_n = 1.f / (float)(NB * HWSZ);
        float mean = sum * inv_n;
        float var = sq * inv_n - mean * mean;
        float inv = rsqrtf(var + BNEPS);
        float scl = gam[c] * inv;
        sc_scaleA[c] = scl;
        sc_shiftA[c] = bet[c] - mean * scl;
    }
}

// ---------------- K3: fold base BN into 1x1 conv weights ----------------
__global__ void k3_fold(const float* __restrict__ Wc, const float* __restrict__ bc,
                        const float* __restrict__ Wr, const float* __restrict__ br) {
    __shared__ float red[256];
    int o = blockIdx.x, ci = threadIdx.x;
    const float* Ws;
    float bs;
    int ol;
    if (o < NCLS) { Ws = Wc; ol = o; bs = bc[o]; }
    else { Ws = Wr; ol = o - NCLS; bs = br[ol]; }
    float w = Ws[ol * CIN + ci];
    sc_Wf[o * CIN + ci] = w * sc_scaleA[ci];
    float tot = block_reduce(w * sc_shiftA[ci], red, ci);
    if (ci == 0) sc_bf[o] = bs + tot;
}

// ---------------- K4m: merged 1x1 convs (cls+reg), f32x2 packed, single read of sc_base ----------------
#define K4_SMEM (CIN * 56 * 4)
__global__ void __launch_bounds__(256) k4m() {
    extern __shared__ float swf[];  // [c][56]
    int tid = threadIdx.x;
    for (int i = tid; i < CIN * 56; i += 256) {
        int c = i / 56, o = i - c * 56;
        swf[i] = (o < NTOT) ? sc_Wf[o * CIN + c] : 0.f;
    }
    __syncthreads();
    int pstart = blockIdx.x * 512;     // 256 thr x 2 px
    int n = pstart >> 14;
    int hwb = (pstart & 16383) + tid;  // px at hwb, hwb+256

    unsigned long long acc2[27][2];
#pragma unroll
    for (int op = 0; op < 27; op++) {
        unsigned long long b = pk2ab(sc_bf[2 * op], sc_bf[2 * op + 1]);
        acc2[op][0] = b;
        acc2[op][1] = b;
    }
    const float* bpn = sc_base + (size_t)n * OCB * HWSZ + hwb;
#pragma unroll 1
    for (int c = 0; c < CIN; c += 8) {
        float v0[8], v1[8];
#pragma unroll
        for (int u = 0; u < 8; u++) {
            const float* p = bpn + (size_t)(c + u) * HWSZ;
            v0[u] = p[0];
            v1[u] = p[256];
        }
#pragma unroll
        for (int u = 0; u < 8; u++) {
            unsigned long long p0 = pk2(v0[u]), p1 = pk2(v1[u]);
            const unsigned long long* wrow = (const unsigned long long*)(swf + (c + u) * 56);
#pragma unroll
            for (int op = 0; op < 27; op++) {
                unsigned long long w = wrow[op];
                fma2(acc2[op][0], w, p0);
                fma2(acc2[op][1], w, p1);
            }
        }
    }
#pragma unroll
    for (int op = 0; op < 27; op++)
#pragma unroll
        for (int px = 0; px < 2; px++) {
            float2 u = upk(acc2[op][px]);
            int ch0 = 2 * op, ch1 = 2 * op + 1;
            size_t idx = hwb + px * 256;
            if (ch0 < NCLS) sc_cls[(size_t)(n * NCLS + ch0) * HWSZ + idx] = u.x;
            else sc_reg[(size_t)(n * NREG + (ch0 - NCLS)) * HWSZ + idx] = u.x;
            if (ch1 < NCLS) sc_cls[(size_t)(n * NCLS + ch1) * HWSZ + idx] = u.y;
            else sc_reg[(size_t)(n * NREG + (ch1 - NCLS)) * HWSZ + idx] = u.y;
        }
}

// ---------------- K5: cls/reg BN stats ----------------
__global__ void k5_stats2(const float* __restrict__ gc, const float* __restrict__ bc,
                          const float* __restrict__ gr, const float* __restrict__ br) {
    __shared__ float red[256];
    int b = blockIdx.x, tid = threadIdx.x;
    const float* src;
    int nch, ch;
    float gam, bet;
    if (b < NCLS) { src = sc_cls; nch = NCLS; ch = b; gam = gc[ch]; bet = bc[ch]; }
    else { src = sc_reg; nch = NREG; ch = b - NCLS; gam = gr[ch]; bet = br[ch]; }
    float s = 0.f;
    for (int n = 0; n < NB; n++) {
        const float* p = &src[(size_t)(n * nch + ch) * HWSZ];
        for (int i = tid; i < HWSZ; i += 256) s += p[i];
    }
    float mean = block_reduce(s, red, tid) * (1.f / (NB * HWSZ));
    s = 0.f;
    for (int n = 0; n < NB; n++) {
        const float* p = &src[(size_t)(n * nch + ch) * HWSZ];
        for (int i = tid; i < HWSZ; i += 256) {
            float d = p[i] - mean;
            s += d * d;
        }
    }
    float var = block_reduce(s, red, tid) * (1.f / (NB * HWSZ));
    if (tid == 0) {
        float inv = rsqrtf(var + BNEPS);
        float scl = gam * inv;
        sc_s2[b] = scl;
        sc_h2[b] = bet - mean * scl;
    }
}

// ---------------- K6: softmax + anchor decode ----------------
__constant__ float c_wa[9] = {455.f, 911.f, 1823.f, 319.f, 639.f, 1279.f, 223.f, 447.f, 895.f};
__constant__ float c_ha[9] = {223.f, 447.f, 895.f, 319.f, 639.f, 1279.f, 447.f, 895.f, 1791.f};

__global__ void k6_decode(const int* __restrict__ imgsz, float* __restrict__ out) {
    int t = blockIdx.x * 256 + threadIdx.x;
    if (t >= NB * HWSZ) return;
    int n = t >> 14, hw = t & 16383;
    int hy = hw >> 7, wx = hw & 127;
    float lim = 2048.f;
    if (imgsz) {
        int iv = *imgsz;
        lim = (iv > 0 && iv < (1 << 24)) ? (float)iv : __int_as_float(iv);
    }
    float cls[NCLS], rg[NREG];
#pragma unroll
    for (int o = 0; o < NCLS; o++)
        cls[o] = sc_cls[(size_t)(n * NCLS + o) * HWSZ + hw] * sc_s2[o] + sc_h2[o];
#pragma unroll
    for (int o = 0; o < NREG; o++)
        rg[o] = sc_reg[(size_t)(n * NREG + o) * HWSZ + hw] * sc_s2[NCLS + o] + sc_h2[NCLS + o];

    const size_t K = (size_t)HWSZ * 9;
    float* fg = out;
    float* ts = out + (size_t)NB * K;
    float* ro = ts + (size_t)NB * K * 4;
    size_t kb = (size_t)n * K + (size_t)hw * 9;

    float cxa = 19.5f + 16.f * (float)wx;
    float cya = 19.5f + 16.f * (float)hy;
#pragma unroll
    for (int a = 0; a < 9; a++) {
        float wa = c_wa[a], ha = c_ha[a];
        float x1 = fminf(fmaxf(rg[a * 4 + 0] + (cxa - 0.5f * wa), 0.f), lim);
        float y1 = fminf(fmaxf(rg[a * 4 + 1] + (cya - 0.5f * ha), 0.f), lim);
        float x2 = fminf(fmaxf(rg[a * 4 + 2] + (cxa + 0.5f * wa), 0.f), lim);
        float y2 = fminf(fmaxf(rg[a * 4 + 3] + (cya + 0.5f * ha), 0.f), lim);
        float w = x2 - x1, h = y2 - y1;
        float cx = x1 + 0.5f * w, cy = y1 + 0.5f * h;
        float s0 = cls[a * 2], s1 = cls[a * 2 + 1];
        fg[kb + a] = 1.f / (1.f + expf(s0 - s1));
        size_t o4 = (kb + a) * 4;
        ts[o4 + 0] = (cx - cxa) / wa;
        ts[o4 + 1] = (cy - cya) / ha;
        ts[o4 + 2] = logf(fmaxf(w / wa, 1e-30f));
        ts[o4 + 3] = logf(fmaxf(h / ha, 1e-30f));
        ro[o4 + 0] = cx;
        ro[o4 + 1] = cy;
        ro[o4 + 2] = w;
        ro[o4 + 3] = h;
    }
}

// ---------------- launch ----------------
extern "C" void kernel_launch(void* const* d_in, const int* in_sizes, int n_in,
                              void* d_out, int out_size) {
    const float* x   = (const float*)d_in[0];
    const float* Wb  = (const float*)d_in[1];
    const float* bb  = (const float*)d_in[2];
    const float* gb  = (const float*)d_in[3];
    const float* beb = (const float*)d_in[4];
    const float* Wc  = (const float*)d_in[5];
    const float* bc  = (const float*)d_in[6];
    const float* gc  = (const float*)d_in[7];
    const float* bec = (const float*)d_in[8];
    const float* Wr  = (const float*)d_in[9];
    const float* br  = (const float*)d_in[10];
    const float* gr  = (const float*)d_in[11];
    const float* ber = (const float*)d_in[12];
    const int* imgsz = (n_in > 13) ? (const int*)d_in[13] : nullptr;
    float* out = (float*)d_out;

    static int smem_set = 0;
    if (!smem_set) {
        cudaFuncSetAttribute(kconv, cudaFuncAttributeMaxDynamicSharedMemorySize, CONV_SMEM);
        cudaFuncSetAttribute(k4m, cudaFuncAttributeMaxDynamicSharedMemorySize, K4_SMEM);
        smem_set = 1;
    }

    dim3 gp(4, 128, NB);
    kP<<<gp, 256>>>(x);
    kW<<<9 * OCB, 256>>>(Wb);

    dim3 gc2(512, 2);
    kconv<<<gc2, 256, CONV_SMEM>>>(bb);

    k2_base_stats<<<OCB, 256>>>(gb, beb);
    k3_fold<<<NTOT, 256>>>(Wc, bc, Wr, br);

    k4m<<<NB * HWSZ / 512, 256, K4_SMEM>>>();

    k5_stats2<<<NTOT, 256>>>(gc, bec, gr, ber);
    k6_decode<<<NB * HWSZ / 256, 256>>>(imgsz, out);
}

// round 11
// speedup vs baseline: 3.6613x; 1.0020x over previous
#include <cuda_runtime.h>
#include <cuda_fp16.h>
#include <cstdint>
#include <math.h>

#define NB 8
#define CIN 256
#define HH 128
#define WW 128
#define HWSZ 16384
#define OCB 256
#define NCLS 18
#define NREG 36
#define NTOT 54
#define BNEPS 1e-5f
#define PW 130          // padded H/W

// ---------------- scratch (device globals; zero-initialized at load) ----------------
// chunk-major padded input: [n][chunk 8][h 130][w 130][32 ci as 8B-units e'=swizzled]
__device__ __half sc_pad[(size_t)NB * 8 * PW * PW * 32];
// weights: [chunk 8][tap 9][oc 256][32 ci swizzled]
__device__ __half sc_Wp[8 * 9 * OCB * 32];
__device__ float sc_base[(size_t)NB * OCB * HWSZ];     // conv3x3+mish output (pre-BN), NCHW
__device__ float sc_part[256][512][2];                 // per-CTA (sum, sumsq) partials per channel
__device__ float sc_cls[(size_t)NB * NCLS * HWSZ];
__device__ float sc_reg[(size_t)NB * NREG * HWSZ];
__device__ float sc_scaleA[CIN];
__device__ float sc_shiftA[CIN];
__device__ float sc_Wf[NTOT * CIN];
__device__ float sc_bf[NTOT];
__device__ float sc_s2[NTOT];
__device__ float sc_h2[NTOT];

// ---------------- helpers ----------------
__device__ __forceinline__ uint32_t smem_u32(const void* p) {
    return (uint32_t)__cvta_generic_to_shared(p);
}
__device__ __forceinline__ unsigned long long pk2(float v) {
    unsigned long long r; unsigned u = __float_as_uint(v);
    asm("mov.b64 %0, {%1, %2};" : "=l"(r) : "r"(u), "r"(u));
    return r;
}
__device__ __forceinline__ unsigned long long pk2ab(float a, float b) {
    unsigned long long r;
    asm("mov.b64 %0, {%1, %2};" : "=l"(r) : "r"(__float_as_uint(a)), "r"(__float_as_uint(b)));
    return r;
}
__device__ __forceinline__ void fma2(unsigned long long& d, unsigned long long a, unsigned long long b) {
    asm("fma.rn.f32x2 %0, %1, %2, %0;" : "+l"(d) : "l"(a), "l"(b));
}
__device__ __forceinline__ float2 upk(unsigned long long v) {
    unsigned lo, hi;
    asm("mov.b64 {%0, %1}, %2;" : "=r"(lo), "=r"(hi) : "l"(v));
    return make_float2(__uint_as_float(lo), __uint_as_float(hi));
}
__device__ __forceinline__ float mishf(float v) {
    float sp = fmaxf(v, 0.f) + log1pf(expf(-fabsf(v)));
    return v * tanhf(sp);
}
__device__ __forceinline__ float block_reduce(float v, float* red, int tid) {
    red[tid] = v; __syncthreads();
#pragma unroll
    for (int o = 128; o > 0; o >>= 1) {
        if (tid < o) red[tid] += red[tid + o];
        __syncthreads();
    }
    float r = red[0];
    __syncthreads();
    return r;
}
// within-16 permutation for m16n8k16 frags: (2kc,2kc+1,2kc+8,2kc+9) contiguous per kc
__device__ __forceinline__ int pidx16(int k) {
    return (k < 8) ? ((k >> 1) * 4 + (k & 1)) : (((k - 8) >> 1) * 4 + 2 + (k & 1));
}
__device__ __forceinline__ int pidx32h(int a) {
    return (a & 16) + pidx16(a & 15);
}
// bank swizzle of 8B-unit index by row index p (conflict-free frag loads)
__device__ __forceinline__ int swz(int p) {
    int t = (p >> 1) & 3;
    return t ^ ((t & 1) << 2);
}

#define MBAR_INIT(a, c) \
    asm volatile("mbarrier.init.shared.b64 [%0], %1;" :: "r"((uint32_t)(a)), "r"((uint32_t)(c)) : "memory")
#define MBAR_EXPECT(a, bytes) \
    asm volatile("mbarrier.arrive.expect_tx.shared.b64 _, [%0], %1;" :: "r"((uint32_t)(a)), "r"((uint32_t)(bytes)) : "memory")
#define MBAR_WAIT(a, p) do {                                                         \
    uint32_t _m = (uint32_t)(a), _p = (uint32_t)(p), _d;                             \
    asm volatile("{\n\t.reg .pred q;\n\t"                                            \
        "mbarrier.try_wait.parity.acquire.cta.shared::cta.b64 q, [%1], %2;\n\t"      \
        "selp.b32 %0, 1, 0, q;\n\t}" : "=r"(_d) : "r"(_m), "r"(_p) : "memory");      \
    if (!_d) {                                                                       \
        asm volatile("{\n\t.reg .pred Q;\n\tWL_%=:\n\t"                              \
            "mbarrier.try_wait.parity.acquire.cta.shared::cta.b64 Q, [%0], %1, 0x989680;\n\t" \
            "@Q bra.uni WD_%=;\n\tbra.uni WL_%=;\n\tWD_%=:\n\t}"                     \
            :: "r"(_m), "r"(_p) : "memory");                                         \
    }                                                                                \
} while (0)

__device__ __forceinline__ void bulk_cp(uint32_t dst, const void* src, uint32_t bytes, uint32_t mbar) {
    asm volatile(
        "cp.async.bulk.shared::cluster.global.mbarrier::complete_tx::bytes [%0], [%1], %2, [%3];"
        :: "r"(dst), "l"(src), "r"(bytes), "r"(mbar) : "memory");
}

// ---------------- kP: NCHW -> chunk-major padded fp16, k-permuted + bank-swizzled ----------------
__global__ void kP(const float* __restrict__ x) {
    __shared__ float t[32][33];
    int n = blockIdx.z, h = blockIdx.y, w0 = blockIdx.x * 32;
    int tid = threadIdx.x;
    int a = tid & 31, b = tid >> 5;  // b: 0..7
    int pc = pidx32h(a);
    int e = pc >> 2, hf = pc & 3;
    for (int c0 = 0; c0 < CIN; c0 += 32) {
        int ch = c0 >> 5;
        __syncthreads();
#pragma unroll
        for (int j = 0; j < 4; j++) {
            int c = c0 + b + j * 8;
            t[b + j * 8][a] = x[(((size_t)n * CIN + c) * HH + h) * WW + w0 + a];
        }
        __syncthreads();
#pragma unroll
        for (int j = 0; j < 4; j++) {
            int wp = w0 + b + j * 8 + 1;
            int ep = e ^ swz(wp);
            size_t idx = ((((size_t)n * 8 + ch) * PW + (h + 1)) * PW + wp) * 32 + ep * 4 + hf;
            sc_pad[idx] = __float2half_rn(t[a][b + j * 8]);
        }
    }
}

// ---------------- kW: W[oc][ci][3][3] -> Wp[chunk][tap][oc][swizzled 32] ----------------
__global__ void kW(const float* __restrict__ W) {
    int bi = blockIdx.x;            // 0..2303
    int oc = bi & 255, tap = bi >> 8;
    int ci = threadIdx.x;
    int ch = ci >> 5, c32 = ci & 31;
    int pc = pidx32h(c32);
    int ep = (pc >> 2) ^ swz(oc & 7);
    sc_Wp[(((size_t)ch * 9 + tap) * OCB + oc) * 32 + ep * 4 + (pc & 3)] =
        __float2half_rn(W[((size_t)oc * CIN + ci) * 9 + tap]);
}

// ---------------- kconv: fp16 m16n8k16, bulk-copy staged, conflict-free frags ----------------
// CTA: 256 thr, 8 warps (wm 0..3 x wn 0..1). Tile M=256 (2 out rows) x N=128 oc.
// Stage = one ci-chunk: A[4 rows][130][64B] (4x8320B) + B[9 taps][128 oc][64B] (9x8192B)
#define A_ROW_H   4160          // halves per A row (130*32)
#define A_H       16640         // halves per A tile (4 rows)
#define B_TAP_H   4096          // halves per B tap (128*32)
#define STAGE_H   53504         // halves per stage (A_H + 9*B_TAP_H)
#define STAGE_BYTES 107008u
#define MBAR_OFF  214016u
#define CONV_SMEM 214048

__device__ __forceinline__ void issue_bulk(const __half* __restrict__ padn,
                                           const __half* __restrict__ wpn,
                                           int h0, int by, int ch,
                                           uint32_t smbase, int buf, uint32_t mbar) {
    MBAR_EXPECT(mbar, STAGE_BYTES);
    uint32_t dst = smbase + (uint32_t)buf * STAGE_BYTES;
    const __half* asrc = padn + ((size_t)ch * PW + h0) * (PW * 32);
#pragma unroll
    for (int r = 0; r < 4; r++)
        bulk_cp(dst + r * 8320u, asrc + (size_t)r * A_ROW_H, 8320u, mbar);
    const __half* bsrc = wpn + (((size_t)ch * 9) * OCB + by * 128) * 32;
#pragma unroll
    for (int tp = 0; tp < 9; tp++)
        bulk_cp(dst + 33280u + tp * 8192u, bsrc + (size_t)tp * OCB * 32, 8192u, mbar);
}

__global__ void __launch_bounds__(256, 1) kconv(const float* __restrict__ pb) {
    extern __shared__ __half smh[];
    uint32_t smbase = smem_u32(smh);
    int tid = threadIdx.x, lane = tid & 31;
    int wid = tid >> 5;
    int wm = wid & 3, wn = wid >> 2;
    int s = blockIdx.x;
    int n = s >> 6, h0 = (s & 63) * 2;
    int by = blockIdx.y;
    const __half* padn = sc_pad + (size_t)n * 8 * PW * PW * 32;

    float acc[4][8][4];
#pragma unroll
    for (int a = 0; a < 4; a++)
#pragma unroll
        for (int b = 0; b < 8; b++)
#pragma unroll
            for (int c = 0; c < 4; c++) acc[a][b][c] = 0.f;

    int mrow = lane >> 2, kc = lane & 3;
    int ro = wm >> 1;                         // out-row offset 0..1
    int pbase = (wm & 1) * 64 + mrow;         // + mf*16 + dx
    int brow = wn * 64 + mrow;                // + nf*8
    int xB = swz(mrow);

    uint32_t mb0 = smbase + MBAR_OFF, mb1 = mb0 + 8;
    if (tid == 0) {
        MBAR_INIT(mb0, 1);
        MBAR_INIT(mb1, 1);
    }
    __syncthreads();
    if (tid == 0) {
        issue_bulk(padn, sc_Wp, h0, by, 0, smbase, 0, mb0);
        issue_bulk(padn, sc_Wp, h0, by, 1, smbase, 1, mb1);
    }

#pragma unroll 1
    for (int st = 0; st < 8; st++) {
        MBAR_WAIT(st & 1 ? mb1 : mb0, (st >> 1) & 1);

        const __half* A = smh + (st & 1) * STAGE_H;
        const __half* B = A + A_H;
#pragma unroll
        for (int dy = 0; dy < 3; dy++) {
            const __half* Arow = A + (ro + dy) * A_ROW_H;
#pragma unroll
            for (int dx = 0; dx < 3; dx++) {
                int xA = swz((mrow + dx) & 7);
                const __half* Bt = B + (dy * 3 + dx) * B_TAP_H;
#pragma unroll
                for (int ks = 0; ks < 2; ks++) {
                    int eA = ((ks * 4 + kc) ^ xA) * 4;
                    int eB = ((ks * 4 + kc) ^ xB) * 4;
                    uint32_t af[4][4];
#pragma unroll
                    for (int mf = 0; mf < 4; mf++) {
                        int p = pbase + mf * 16 + dx;
                        const uint2* plo = (const uint2*)(Arow + p * 32 + eA);
                        uint2 lo = plo[0];
                        uint2 hi = *(const uint2*)((const __half*)plo + 256);  // p+8
                        af[mf][0] = lo.x;
                        af[mf][1] = hi.x;
                        af[mf][2] = lo.y;
                        af[mf][3] = hi.y;
                    }
                    uint32_t bfr[8][2];
#pragma unroll
                    for (int nf = 0; nf < 8; nf++) {
                        uint2 bv = *(const uint2*)(Bt + (brow + nf * 8) * 32 + eB);
                        bfr[nf][0] = bv.x;
                        bfr[nf][1] = bv.y;
                    }
#pragma unroll
                    for (int mf = 0; mf < 4; mf++)
#pragma unroll
                        for (int nf = 0; nf < 8; nf++)
                            asm volatile(
                                "mma.sync.aligned.m16n8k16.row.col.f32.f16.f16.f32 "
                                "{%0,%1,%2,%3}, {%4,%5,%6,%7}, {%8,%9}, {%0,%1,%2,%3};"
                                : "+f"(acc[mf][nf][0]), "+f"(acc[mf][nf][1]),
                                  "+f"(acc[mf][nf][2]), "+f"(acc[mf][nf][3])
                                : "r"(af[mf][0]), "r"(af[mf][1]), "r"(af[mf][2]), "r"(af[mf][3]),
                                  "r"(bfr[nf][0]), "r"(bfr[nf][1]));
                }
            }
        }
        __syncthreads();
        if (st + 2 < 8 && tid == 0)
            issue_bulk(padn, sc_Wp, h0, by, st + 2, smbase, st & 1, st & 1 ? mb1 : mb0);
    }

    // epilogue: bias + mish -> sc_base NCHW, plus deterministic per-channel stats partials
    int h = h0 + ro;
    float ssum[8][2], ssq[8][2];
#pragma unroll
    for (int nf = 0; nf < 8; nf++) {
        ssum[nf][0] = ssum[nf][1] = 0.f;
        ssq[nf][0] = ssq[nf][1] = 0.f;
    }
#pragma unroll
    for (int mf = 0; mf < 4; mf++) {
        int w = (wm & 1) * 64 + mf * 16 + mrow;
#pragma unroll
        for (int nf = 0; nf < 8; nf++) {
            int oc = by * 128 + wn * 64 + nf * 8 + 2 * kc;
            float b0v = pb[oc], b1v = pb[oc + 1];
            float v0 = mishf(acc[mf][nf][0] + b0v);
            float v1 = mishf(acc[mf][nf][1] + b1v);
            float v2 = mishf(acc[mf][nf][2] + b0v);
            float v3 = mishf(acc[mf][nf][3] + b1v);
            float* p = sc_base + ((size_t)(n * OCB + oc)) * HWSZ + h * WW + w;
            p[0] = v0; p[HWSZ] = v1; p[8] = v2; p[HWSZ + 8] = v3;
            ssum[nf][0] += v0 + v2;  ssq[nf][0] += v0 * v0 + v2 * v2;
            ssum[nf][1] += v1 + v3;  ssq[nf][1] += v1 * v1 + v3 * v3;
        }
    }
#pragma unroll
    for (int off = 4; off <= 16; off <<= 1) {
#pragma unroll
        for (int nf = 0; nf < 8; nf++)
#pragma unroll
            for (int j = 0; j < 2; j++) {
                ssum[nf][j] += __shfl_xor_sync(0xffffffffu, ssum[nf][j], off);
                ssq[nf][j] += __shfl_xor_sync(0xffffffffu, ssq[nf][j], off);
            }
    }
    float* part = (float*)smh;  // overlay [wn][wm][64 chl][2]
    __syncthreads();
    if (mrow == 0) {
#pragma unroll
        for (int nf = 0; nf < 8; nf++)
#pragma unroll
            for (int j = 0; j < 2; j++) {
                int chl = nf * 8 + 2 * kc + j;
                part[((wn * 4 + wm) * 64 + chl) * 2 + 0] = ssum[nf][j];
                part[((wn * 4 + wm) * 64 + chl) * 2 + 1] = ssq[nf][j];
            }
    }
    __syncthreads();
    {
        int wn2 = tid >> 7, chl = (tid >> 1) & 63, v = tid & 1;
        float t = 0.f;
#pragma unroll
        for (int wm2 = 0; wm2 < 4; wm2++)
            t += part[((wn2 * 4 + wm2) * 64 + chl) * 2 + v];
        sc_part[by * 128 + wn2 * 64 + chl][s][v] = t;
    }
}

// ---------------- K2: base BN stats from partials (deterministic fixed-order) ----------------
__global__ void k2_base_stats(const float* __restrict__ gam, const float* __restrict__ bet) {
    __shared__ float red[256];
    int c = blockIdx.x, tid = threadIdx.x;
    float s = sc_part[c][tid][0] + sc_part[c][tid + 256][0];
    float sum = block_reduce(s, red, tid);
    float q = sc_part[c][tid][1] + sc_part[c][tid + 256][1];
    float sq = block_reduce(q, red, tid);
    if (tid == 0) {
        float inv_n = 1.f / (float)(NB * HWSZ);
        float mean = sum * inv_n;
        float var = sq * inv_n - mean * mean;
        float inv = rsqrtf(var + BNEPS);
        float scl = gam[c] * inv;
        sc_scaleA[c] = scl;
        sc_shiftA[c] = bet[c] - mean * scl;
    }
}

// ---------------- K3: fold base BN into 1x1 conv weights ----------------
__global__ void k3_fold(const float* __restrict__ Wc, const float* __restrict__ bc,
                        const float* __restrict__ Wr, const float* __restrict__ br) {
    __shared__ float red[256];
    int o = blockIdx.x, ci = threadIdx.x;
    const float* Ws;
    float bs;
    int ol;
    if (o < NCLS) { Ws = Wc; ol = o; bs = bc[o]; }
    else { Ws = Wr; ol = o - NCLS; bs = br[ol]; }
    float w = Ws[ol * CIN + ci];
    sc_Wf[o * CIN + ci] = w * sc_scaleA[ci];
    float tot = block_reduce(w * sc_shiftA[ci], red, ci);
    if (ci == 0) sc_bf[o] = bs + tot;
}

// ---------------- K4m: merged 1x1 convs (cls+reg), f32x2 packed, single read of sc_base ----------------
#define K4_SMEM (CIN * 56 * 4)
__global__ void __launch_bounds__(256) k4m() {
    extern __shared__ float swf[];  // [c][56]
    int tid = threadIdx.x;
    for (int i = tid; i < CIN * 56; i += 256) {
        int c = i / 56, o = i - c * 56;
        swf[i] = (o < NTOT) ? sc_Wf[o * CIN + c] : 0.f;
    }
    __syncthreads();
    int pstart = blockIdx.x * 512;     // 256 thr x 2 px
    int n = pstart >> 14;
    int hwb = (pstart & 16383) + tid;  // px at hwb, hwb+256

    unsigned long long acc2[27][2];
#pragma unroll
    for (int op = 0; op < 27; op++) {
        unsigned long long b = pk2ab(sc_bf[2 * op], sc_bf[2 * op + 1]);
        acc2[op][0] = b;
        acc2[op][1] = b;
    }
    const float* bpn = sc_base + (size_t)n * OCB * HWSZ + hwb;
#pragma unroll 1
    for (int c = 0; c < CIN; c += 8) {
        float v0[8], v1[8];
#pragma unroll
        for (int u = 0; u < 8; u++) {
            const float* p = bpn + (size_t)(c + u) * HWSZ;
            v0[u] = p[0];
            v1[u] = p[256];
        }
#pragma unroll
        for (int u = 0; u < 8; u++) {
            unsigned long long p0 = pk2(v0[u]), p1 = pk2(v1[u]);
            const unsigned long long* wrow = (const unsigned long long*)(swf + (c + u) * 56);
#pragma unroll
            for (int op = 0; op < 27; op++) {
                unsigned long long w = wrow[op];
                fma2(acc2[op][0], w, p0);
                fma2(acc2[op][1], w, p1);
            }
        }
    }
#pragma unroll
    for (int op = 0; op < 27; op++)
#pragma unroll
        for (int px = 0; px < 2; px++) {
            float2 u = upk(acc2[op][px]);
            int ch0 = 2 * op, ch1 = 2 * op + 1;
            size_t idx = hwb + px * 256;
            if (ch0 < NCLS) sc_cls[(size_t)(n * NCLS + ch0) * HWSZ + idx] = u.x;
            else sc_reg[(size_t)(n * NREG + (ch0 - NCLS)) * HWSZ + idx] = u.x;
            if (ch1 < NCLS) sc_cls[(size_t)(n * NCLS + ch1) * HWSZ + idx] = u.y;
            else sc_reg[(size_t)(n * NREG + (ch1 - NCLS)) * HWSZ + idx] = u.y;
        }
}

// ---------------- K5: cls/reg BN stats ----------------
__global__ void k5_stats2(const float* __restrict__ gc, const float* __restrict__ bc,
                          const float* __restrict__ gr, const float* __restrict__ br) {
    __shared__ float red[256];
    int b = blockIdx.x, tid = threadIdx.x;
    const float* src;
    int nch, ch;
    float gam, bet;
    if (b < NCLS) { src = sc_cls; nch = NCLS; ch = b; gam = gc[ch]; bet = bc[ch]; }
    else { src = sc_reg; nch = NREG; ch = b - NCLS; gam = gr[ch]; bet = br[ch]; }
    float s = 0.f;
    for (int n = 0; n < NB; n++) {
        const float* p = &src[(size_t)(n * nch + ch) * HWSZ];
        for (int i = tid; i < HWSZ; i += 256) s += p[i];
    }
    float mean = block_reduce(s, red, tid) * (1.f / (NB * HWSZ));
    s = 0.f;
    for (int n = 0; n < NB; n++) {
        const float* p = &src[(size_t)(n * nch + ch) * HWSZ];
        for (int i = tid; i < HWSZ; i += 256) {
            float d = p[i] - mean;
            s += d * d;
        }
    }
    float var = block_reduce(s, red, tid) * (1.f / (NB * HWSZ));
    if (tid == 0) {
        float inv = rsqrtf(var + BNEPS);
        float scl = gam * inv;
        sc_s2[b] = scl;
        sc_h2[b] = bet - mean * scl;
    }
}

// ---------------- K6: softmax + anchor decode ----------------
__constant__ float c_wa[9] = {455.f, 911.f, 1823.f, 319.f, 639.f, 1279.f, 223.f, 447.f, 895.f};
__constant__ float c_ha[9] = {223.f, 447.f, 895.f, 319.f, 639.f, 1279.f, 447.f, 895.f, 1791.f};

__global__ void k6_decode(const int* __restrict__ imgsz, float* __restrict__ out) {
    int t = blockIdx.x * 256 + threadIdx.x;
    if (t >= NB * HWSZ) return;
    int n = t >> 14, hw = t & 16383;
    int hy = hw >> 7, wx = hw & 127;
    float lim = 2048.f;
    if (imgsz) {
        int iv = *imgsz;
        lim = (iv > 0 && iv < (1 << 24)) ? (float)iv : __int_as_float(iv);
    }
    float cls[NCLS], rg[NREG];
#pragma unroll
    for (int o = 0; o < NCLS; o++)
        cls[o] = sc_cls[(size_t)(n * NCLS + o) * HWSZ + hw] * sc_s2[o] + sc_h2[o];
#pragma unroll
    for (int o = 0; o < NREG; o++)
        rg[o] = sc_reg[(size_t)(n * NREG + o) * HWSZ + hw] * sc_s2[NCLS + o] + sc_h2[NCLS + o];

    const size_t K = (size_t)HWSZ * 9;
    float* fg = out;
    float* ts = out + (size_t)NB * K;
    float* ro = ts + (size_t)NB * K * 4;
    size_t kb = (size_t)n * K + (size_t)hw * 9;

    float cxa = 19.5f + 16.f * (float)wx;
    float cya = 19.5f + 16.f * (float)hy;
#pragma unroll
    for (int a = 0; a < 9; a++) {
        float wa = c_wa[a], ha = c_ha[a];
        float x1 = fminf(fmaxf(rg[a * 4 + 0] + (cxa - 0.5f * wa), 0.f), lim);
        float y1 = fminf(fmaxf(rg[a * 4 + 1] + (cya - 0.5f * ha), 0.f), lim);
        float x2 = fminf(fmaxf(rg[a * 4 + 2] + (cxa + 0.5f * wa), 0.f), lim);
        float y2 = fminf(fmaxf(rg[a * 4 + 3] + (cya + 0.5f * ha), 0.f), lim);
        float w = x2 - x1, h = y2 - y1;
        float cx = x1 + 0.5f * w, cy = y1 + 0.5f * h;
        float s0 = cls[a * 2], s1 = cls[a * 2 + 1];
        fg[kb + a] = 1.f / (1.f + expf(s0 - s1));
        size_t o4 = (kb + a) * 4;
        ts[o4 + 0] = (cx - cxa) / wa;
        ts[o4 + 1] = (cy - cya) / ha;
        ts[o4 + 2] = logf(fmaxf(w / wa, 1e-30f));
        ts[o4 + 3] = logf(fmaxf(h / ha, 1e-30f));
        ro[o4 + 0] = cx;
        ro[o4 + 1] = cy;
        ro[o4 + 2] = w;
        ro[o4 + 3] = h;
    }
}

// ---------------- launch ----------------
extern "C" void kernel_launch(void* const* d_in, const int* in_sizes, int n_in,
                              void* d_out, int out_size) {
    const float* x   = (const float*)d_in[0];
    const float* Wb  = (const float*)d_in[1];
    const float* bb  = (const float*)d_in[2];
    const float* gb  = (const float*)d_in[3];
    const float* beb = (const float*)d_in[4];
    const float* Wc  = (const float*)d_in[5];
    const float* bc  = (const float*)d_in[6];
    const float* gc  = (const float*)d_in[7];
    const float* bec = (const float*)d_in[8];
    const float* Wr  = (const float*)d_in[9];
    const float* br  = (const float*)d_in[10];
    const float* gr  = (const float*)d_in[11];
    const float* ber = (const float*)d_in[12];
    const int* imgsz = (n_in > 13) ? (const int*)d_in[13] : nullptr;
    float* out = (float*)d_out;

    static int smem_set = 0;
    if (!smem_set) {
        cudaFuncSetAttribute(kconv, cudaFuncAttributeMaxDynamicSharedMemorySize, CONV_SMEM);
        cudaFuncSetAttribute(k4m, cudaFuncAttributeMaxDynamicSharedMemorySize, K4_SMEM);
        smem_set = 1;
    }

    dim3 gp(4, 128, NB);
    kP<<<gp, 256>>>(x);
    kW<<<9 * OCB, 256>>>(Wb);

    dim3 gc2(512, 2);
    kconv<<<gc2, 256, CONV_SMEM>>>(bb);

    k2_base_stats<<<OCB, 256>>>(gb, beb);
    k3_fold<<<NTOT, 256>>>(Wc, bc, Wr, br);

    k4m<<<NB * HWSZ / 512, 256, K4_SMEM>>>();

    k5_stats2<<<NTOT, 256>>>(gc, bec, gr, ber);
    k6_decode<<<NB * HWSZ / 256, 256>>>(imgsz, out);
}